// round 2
// baseline (speedup 1.0000x reference)
#include <cuda_runtime.h>
#include <cuda_bf16.h>
#include <math.h>

// Problem constants
#define B_  2
#define N_  2048
#define D_  1024
#define H_  16
#define DH_ 64
#define ROWS_ (B_*N_)          // 4096
#define BHN_  (B_*H_*N_)       // 65536

#define QB 128   // q rows per attention CTA
#define KT 64    // key tile
#define CH 16    // score chunk held in registers

// Scratch (static device globals — no allocation)
__device__ float g_q[B_*H_*N_*DH_];
__device__ float g_k[B_*H_*N_*DH_];
__device__ float g_v[B_*H_*N_*DH_];
__device__ float g_ctx[B_*N_*D_];
__device__ float g_kn[BHN_];

__device__ __forceinline__ float softplusf(float x) {
    return (x > 20.f) ? x : log1pf(__expf(x));
}

// ---------------------------------------------------------------------------
// SGEMM: out = A[4096,1024] @ W[1024,1024]^T
// BM=BN=128, BK=16, 256 threads, 8x8 microtile, double-buffered smem.
// blockIdx.z selects (W, C). headLayout writes [B,H,N,Dh].
// ---------------------------------------------------------------------------
__global__ __launch_bounds__(256, 2)
void sgemm_xwt(const float* __restrict__ A,
               const float* __restrict__ W0, const float* __restrict__ W1,
               const float* __restrict__ W2,
               float* __restrict__ C0, float* __restrict__ C1,
               float* __restrict__ C2,
               int headLayout)
{
    const int K = D_;
    const float* __restrict__ W = (blockIdx.z == 0) ? W0 : (blockIdx.z == 1) ? W1 : W2;
    float* __restrict__ C       = (blockIdx.z == 0) ? C0 : (blockIdx.z == 1) ? C1 : C2;

    __shared__ float As[2][16][128];
    __shared__ float Bs[2][16][128];

    const int tid = threadIdx.x;
    const int tx = tid & 15;          // N
    const int ty = tid >> 4;          // M
    const int rowBase = blockIdx.y * 128;
    const int colBase = blockIdx.x * 128;

    float4 pa[2], pb[2];

    // Preload tile 0
#pragma unroll
    for (int i = 0; i < 2; i++) {
        int f = tid + i * 256, r = f >> 2, kq = (f & 3) << 2;
        pa[i] = *(const float4*)(A + (size_t)(rowBase + r) * K + kq);
        pb[i] = *(const float4*)(W + (size_t)(colBase + r) * K + kq);
    }
#pragma unroll
    for (int i = 0; i < 2; i++) {
        int f = tid + i * 256, r = f >> 2, kq = (f & 3) << 2;
        As[0][kq + 0][r] = pa[i].x; As[0][kq + 1][r] = pa[i].y;
        As[0][kq + 2][r] = pa[i].z; As[0][kq + 3][r] = pa[i].w;
        Bs[0][kq + 0][r] = pb[i].x; Bs[0][kq + 1][r] = pb[i].y;
        Bs[0][kq + 2][r] = pb[i].z; Bs[0][kq + 3][r] = pb[i].w;
    }
    __syncthreads();

    float acc[8][8];
#pragma unroll
    for (int u = 0; u < 8; u++)
#pragma unroll
        for (int v = 0; v < 8; v++) acc[u][v] = 0.f;

    const int NT = K / 16;   // 64
    for (int kt = 0; kt < NT; kt++) {
        const int cur = kt & 1;
        if (kt + 1 < NT) {
            const int kk = (kt + 1) * 16;
#pragma unroll
            for (int i = 0; i < 2; i++) {
                int f = tid + i * 256, r = f >> 2, kq = (f & 3) << 2;
                pa[i] = *(const float4*)(A + (size_t)(rowBase + r) * K + kk + kq);
                pb[i] = *(const float4*)(W + (size_t)(colBase + r) * K + kk + kq);
            }
        }
#pragma unroll
        for (int k = 0; k < 16; k++) {
            float af[8], bf[8];
            *(float4*)(af)     = *(const float4*)&As[cur][k][ty * 8];
            *(float4*)(af + 4) = *(const float4*)&As[cur][k][ty * 8 + 4];
            *(float4*)(bf)     = *(const float4*)&Bs[cur][k][tx * 8];
            *(float4*)(bf + 4) = *(const float4*)&Bs[cur][k][tx * 8 + 4];
#pragma unroll
            for (int u = 0; u < 8; u++)
#pragma unroll
                for (int v = 0; v < 8; v++)
                    acc[u][v] = fmaf(af[u], bf[v], acc[u][v]);
        }
        if (kt + 1 < NT) {
            const int nxt = cur ^ 1;
#pragma unroll
            for (int i = 0; i < 2; i++) {
                int f = tid + i * 256, r = f >> 2, kq = (f & 3) << 2;
                As[nxt][kq + 0][r] = pa[i].x; As[nxt][kq + 1][r] = pa[i].y;
                As[nxt][kq + 2][r] = pa[i].z; As[nxt][kq + 3][r] = pa[i].w;
                Bs[nxt][kq + 0][r] = pb[i].x; Bs[nxt][kq + 1][r] = pb[i].y;
                Bs[nxt][kq + 2][r] = pb[i].z; Bs[nxt][kq + 3][r] = pb[i].w;
            }
        }
        __syncthreads();
    }

    // Epilogue
#pragma unroll
    for (int u = 0; u < 8; u++) {
        int row = rowBase + ty * 8 + u;
#pragma unroll
        for (int vv = 0; vv < 2; vv++) {
            int col = colBase + tx * 8 + vv * 4;
            float4 val = make_float4(acc[u][vv*4+0], acc[u][vv*4+1],
                                     acc[u][vv*4+2], acc[u][vv*4+3]);
            if (headLayout) {
                int b = row >> 11, n = row & 2047;
                int h = col >> 6,  dh = col & 63;
                *(float4*)(C + (((size_t)(b * H_ + h)) * N_ + n) * DH_ + dh) = val;
            } else {
                *(float4*)(C + (size_t)row * D_ + col) = val;
            }
        }
    }
}

// ---------------------------------------------------------------------------
// K row squared-norms: one warp per 64-elem row.
// ---------------------------------------------------------------------------
__global__ void k_norms(const float* __restrict__ k, float* __restrict__ kn)
{
    int gw = (blockIdx.x * blockDim.x + threadIdx.x) >> 5;
    int lane = threadIdx.x & 31;
    if (gw >= BHN_) return;
    const float* r = k + (size_t)gw * DH_;
    float a = r[lane], b = r[lane + 32];
    float s = a * a + b * b;
#pragma unroll
    for (int off = 16; off > 0; off >>= 1)
        s += __shfl_xor_sync(0xFFFFFFFFu, s, off);
    if (lane == 0) kn[gw] = s;
}

// ---------------------------------------------------------------------------
// Hyperbolic flash attention, fp32.
// grid = (N/QB, B*H), block = QB threads. Thread t owns q-row r0+t.
// Scores held in a CH-deep register chunk; branchless dist; reversed
// blockIdx.x so heavy (long-context) CTAs schedule first.
// ---------------------------------------------------------------------------
__global__ __launch_bounds__(QB)
void hyp_attn(const float* __restrict__ qp, const float* __restrict__ kp,
              const float* __restrict__ vp, const float* __restrict__ knp,
              float* __restrict__ ctx,
              const float* __restrict__ logc_p, const float* __restrict__ logb_p)
{
    __shared__ float ks[KT * DH_];
    __shared__ float vs[KT * DH_];
    __shared__ float kns[KT];

    const int tid = threadIdx.x;
    const int bh  = blockIdx.y;
    const int qb  = (gridDim.x - 1) - blockIdx.x;   // heavy blocks first
    const int r0  = qb * QB;
    const int row = r0 + tid;

    const float c    = softplusf(*logc_p);
    const float beta = softplusf(*logb_p) + 0.5f;

    // Q row into registers; qn from registers.
    float q[DH_];
    {
        const float* qrow = qp + ((size_t)bh * N_ + row) * DH_;
#pragma unroll
        for (int d = 0; d < DH_; d += 4) {
            float4 t = *(const float4*)(qrow + d);
            q[d] = t.x; q[d+1] = t.y; q[d+2] = t.z; q[d+3] = t.w;
        }
    }
    float qn = 0.f;
#pragma unroll
    for (int d = 0; d < DH_; d++) qn = fmaf(q[d], q[d], qn);

    float mprev = -1e30f, l = 0.f;
    float o[DH_];
#pragma unroll
    for (int d = 0; d < DH_; d++) o[d] = 0.f;

    const int ntiles = 2 * qb + 2;
    for (int T = 0; T < ntiles; T++) {
        const int t0 = T * KT;
        __syncthreads();   // protect ks/vs from prior-iteration readers
        {
            const float4* k4 = (const float4*)(kp + ((size_t)bh * N_ + t0) * DH_);
            const float4* v4 = (const float4*)(vp + ((size_t)bh * N_ + t0) * DH_);
            float4* ksd = (float4*)ks;
            float4* vsd = (float4*)vs;
#pragma unroll
            for (int i = 0; i < 8; i++) {
                int f = i * QB + tid;   // 1024 float4 per array
                ksd[f] = k4[f];
                vsd[f] = v4[f];
            }
            if (tid < KT) kns[tid] = knp[bh * N_ + t0 + tid];
        }
        __syncthreads();

        for (int cc = 0; cc < KT / CH; cc++) {
            float s[CH];
            float cmax = -1e30f;
#pragma unroll
            for (int m = 0; m < CH; m++) {
                const int mm = cc * CH + m;
                const float* krow = &ks[mm * DH_];
                float s0 = 0.f, s1 = 0.f, s2 = 0.f, s3 = 0.f;
#pragma unroll
                for (int d = 0; d < DH_; d += 4) {
                    s0 = fmaf(q[d + 0], krow[d + 0], s0);
                    s1 = fmaf(q[d + 1], krow[d + 1], s1);
                    s2 = fmaf(q[d + 2], krow[d + 2], s2);
                    s3 = fmaf(q[d + 3], krow[d + 3], s3);
                }
                float dot = (s0 + s1) + (s2 + s3);
                float kn  = kns[mm];
                float diff = fmaxf(qn - 2.f * dot + kn, 0.f);
                float ed = sqrtf(diff + 1e-8f);
                float ns = qn + kn;
                float cns = c * ns;
                float d_tay = ed * (1.f + 0.5f * cns + 0.125f * cns * cns);
                float d_asy = 0.693f + __logf(ed + 1e-8f) + 0.25f * cns;
                float d_std = ed * sqrtf(1.f + cns);
                float dist = (ed < 0.1f) ? d_tay : ((ed > 2.0f) ? d_asy : d_std);
                float sc = -beta * dist;
                sc = (t0 + mm > row) ? -1e30f : sc;
                s[m] = sc;
                cmax = fmaxf(cmax, sc);
            }
            const float mnew = fmaxf(mprev, cmax);
            const float corr = __expf(mprev - mnew);
            l *= corr;
#pragma unroll
            for (int d = 0; d < DH_; d++) o[d] *= corr;
#pragma unroll
            for (int m = 0; m < CH; m++) {
                float p = __expf(s[m] - mnew);
                l += p;
                const float* vrow = &vs[(cc * CH + m) * DH_];
#pragma unroll
                for (int d = 0; d < DH_; d++)
                    o[d] = fmaf(p, vrow[d], o[d]);
            }
            mprev = mnew;
        }
    }

    // Write ctx[(b*N + row)*D + h*64 + d]
    const float inv = 1.f / l;
    const int b = bh >> 4, h = bh & 15;
    float* outp = ctx + ((size_t)b * N_ + row) * D_ + h * DH_;
#pragma unroll
    for (int d4 = 0; d4 < 16; d4++) {
        float4 val = make_float4(o[d4*4+0]*inv, o[d4*4+1]*inv,
                                 o[d4*4+2]*inv, o[d4*4+3]*inv);
        *(float4*)(outp + d4 * 4) = val;
    }
}

// ---------------------------------------------------------------------------
extern "C" void kernel_launch(void* const* d_in, const int* in_sizes, int n_in,
                              void* d_out, int out_size)
{
    const float* x     = (const float*)d_in[0];
    const float* Wq    = (const float*)d_in[1];
    const float* Wk    = (const float*)d_in[2];
    const float* Wv    = (const float*)d_in[3];
    const float* Wo    = (const float*)d_in[4];
    const float* log_c = (const float*)d_in[5];
    const float* log_b = (const float*)d_in[6];
    float* out = (float*)d_out;

    float *qptr, *kptr, *vptr, *ctxptr, *knp;
    cudaGetSymbolAddress((void**)&qptr,  g_q);
    cudaGetSymbolAddress((void**)&kptr,  g_k);
    cudaGetSymbolAddress((void**)&vptr,  g_v);
    cudaGetSymbolAddress((void**)&ctxptr, g_ctx);
    cudaGetSymbolAddress((void**)&knp,   g_kn);

    // QKV projections (fused into one launch via z)
    dim3 gq(D_ / 128, ROWS_ / 128, 3);
    sgemm_xwt<<<gq, 256>>>(x, Wq, Wk, Wv, qptr, kptr, vptr, 1);

    // K norms
    k_norms<<<BHN_ / 8, 256>>>(kptr, knp);

    // Attention
    hyp_attn<<<dim3(N_ / QB, B_ * H_), QB>>>(qptr, kptr, vptr, knp, ctxptr,
                                             log_c, log_b);

    // Output projection
    dim3 go(D_ / 128, ROWS_ / 128, 1);
    sgemm_xwt<<<go, 256>>>(ctxptr, Wo, Wo, Wo, out, out, out, 0);
}

// round 8
// speedup vs baseline: 1.2341x; 1.2341x over previous
#include <cuda_runtime.h>
#include <cuda_bf16.h>
#include <math.h>

// Problem constants
#define B_  2
#define N_  2048
#define D_  1024
#define H_  16
#define DH_ 64
#define ROWS_ (B_*N_)          // 4096
#define BHN_  (B_*H_*N_)       // 65536

#define QB 128   // q rows per attention CTA (1 thread per row)
#define KT 64    // key tile

typedef unsigned long long ull;

// ---- packed fp32x2 + MUFU approx helpers (sm_103a) ----
#define F2FMA(d, a, b, c) \
    asm("fma.rn.f32x2 %0, %1, %2, %3;" : "=l"(d) : "l"(a), "l"(b), "l"(c))
#define F2ADD(d, a, b) \
    asm("add.rn.f32x2 %0, %1, %2;" : "=l"(d) : "l"(a), "l"(b))
#define F2PACK(d, lo, hi) \
    asm("mov.b64 %0, {%1, %2};" : "=l"(d) : "r"(__float_as_uint(lo)), "r"(__float_as_uint(hi)))
#define F2UNPACK(lo, hi, v) do { unsigned _ulo, _uhi; \
    asm("mov.b64 {%0, %1}, %2;" : "=r"(_ulo), "=r"(_uhi) : "l"(v)); \
    lo = __uint_as_float(_ulo); hi = __uint_as_float(_uhi); } while (0)
__device__ __forceinline__ float sqrt_apx(float x) {
    float r; asm("sqrt.approx.f32 %0, %1;" : "=f"(r) : "f"(x)); return r;
}
__device__ __forceinline__ float lg2_apx(float x) {
    float r; asm("lg2.approx.f32 %0, %1;" : "=f"(r) : "f"(x)); return r;
}
__device__ __forceinline__ float ex2_apx(float x) {
    float r; asm("ex2.approx.f32 %0, %1;" : "=f"(r) : "f"(x)); return r;
}

// Scratch (static device globals — no allocation)
__device__ float g_q[B_*H_*N_*DH_];
__device__ float g_k[B_*H_*N_*DH_];
__device__ float g_v[B_*H_*N_*DH_];
__device__ float g_ctx[B_*N_*D_];
__device__ float g_kn[BHN_];

__device__ __forceinline__ float softplusf(float x) {
    return (x > 20.f) ? x : log1pf(__expf(x));
}

// ---------------------------------------------------------------------------
// SGEMM: out = A[4096,1024] @ W[1024,1024]^T
// BM=BN=128, BK=16, 256 threads, 8x8 microtile, FFMA2 inner loop.
// ---------------------------------------------------------------------------
__global__ __launch_bounds__(256, 2)
void sgemm_xwt(const float* __restrict__ A,
               const float* __restrict__ W0, const float* __restrict__ W1,
               const float* __restrict__ W2,
               float* __restrict__ C0, float* __restrict__ C1,
               float* __restrict__ C2,
               int headLayout)
{
    const int K = D_;
    const float* __restrict__ W = (blockIdx.z == 0) ? W0 : (blockIdx.z == 1) ? W1 : W2;
    float* __restrict__ C       = (blockIdx.z == 0) ? C0 : (blockIdx.z == 1) ? C1 : C2;

    __shared__ float As[16][128];
    __shared__ float Bs[16][128];

    const int tid = threadIdx.x;
    const int tx = tid & 15;          // N
    const int ty = tid >> 4;          // M
    const int rowBase = blockIdx.y * 128;
    const int colBase = blockIdx.x * 128;

    ull acc2[8][4];
#pragma unroll
    for (int u = 0; u < 8; u++)
#pragma unroll
        for (int j = 0; j < 4; j++) acc2[u][j] = 0ull;   // (+0.f,+0.f)

    for (int kk = 0; kk < K; kk += 16) {
#pragma unroll
        for (int i = 0; i < 2; i++) {
            int f  = tid + i * 256;
            int r  = f >> 2;
            int kq = (f & 3) * 4;
            float4 a = *(const float4*)(A + (size_t)(rowBase + r) * K + kk + kq);
            As[kq + 0][r] = a.x; As[kq + 1][r] = a.y;
            As[kq + 2][r] = a.z; As[kq + 3][r] = a.w;
            float4 b = *(const float4*)(W + (size_t)(colBase + r) * K + kk + kq);
            Bs[kq + 0][r] = b.x; Bs[kq + 1][r] = b.y;
            Bs[kq + 2][r] = b.z; Bs[kq + 3][r] = b.w;
        }
        __syncthreads();
#pragma unroll
        for (int k = 0; k < 16; k++) {
            float af[8];
            *(float4*)(af)     = *(const float4*)&As[k][ty * 8];
            *(float4*)(af + 4) = *(const float4*)&As[k][ty * 8 + 4];
            longlong2 b0 = *(const longlong2*)&Bs[k][tx * 8];
            longlong2 b1 = *(const longlong2*)&Bs[k][tx * 8 + 4];
            ull bf2[4];
            bf2[0] = (ull)b0.x; bf2[1] = (ull)b0.y;
            bf2[2] = (ull)b1.x; bf2[3] = (ull)b1.y;
#pragma unroll
            for (int u = 0; u < 8; u++) {
                ull a2; F2PACK(a2, af[u], af[u]);
#pragma unroll
                for (int j = 0; j < 4; j++)
                    F2FMA(acc2[u][j], a2, bf2[j], acc2[u][j]);
            }
        }
        __syncthreads();
    }

    // Epilogue
#pragma unroll
    for (int u = 0; u < 8; u++) {
        int row = rowBase + ty * 8 + u;
        float cv[8];
#pragma unroll
        for (int j = 0; j < 4; j++) F2UNPACK(cv[2*j], cv[2*j+1], acc2[u][j]);
#pragma unroll
        for (int vv = 0; vv < 2; vv++) {
            int col = colBase + tx * 8 + vv * 4;
            float4 val = make_float4(cv[vv*4+0], cv[vv*4+1], cv[vv*4+2], cv[vv*4+3]);
            if (headLayout) {
                int b = row >> 11, n = row & 2047;
                int h = col >> 6,  dh = col & 63;
                *(float4*)(C + (((size_t)(b * H_ + h)) * N_ + n) * DH_ + dh) = val;
            } else {
                *(float4*)(C + (size_t)row * D_ + col) = val;
            }
        }
    }
}

// ---------------------------------------------------------------------------
// K row squared-norms: one warp per 64-elem row.
// ---------------------------------------------------------------------------
__global__ void k_norms(const float* __restrict__ k, float* __restrict__ kn)
{
    int gw = (blockIdx.x * blockDim.x + threadIdx.x) >> 5;
    int lane = threadIdx.x & 31;
    if (gw >= BHN_) return;
    const float* r = k + (size_t)gw * DH_;
    float a = r[lane], b = r[lane + 32];
    float s = a * a + b * b;
#pragma unroll
    for (int off = 16; off > 0; off >>= 1)
        s += __shfl_xor_sync(0xFFFFFFFFu, s, off);
    if (lane == 0) kn[gw] = s;
}

// ---------------------------------------------------------------------------
// One KT-key tile of hyperbolic attention for one q-row (held in q2/o2).
// No running max: scores are always <= 0 and the diagonal keeps l ~ O(1).
// 64 floats = 16 longlong2 per K/V row; loops cover ALL 16 (R5 bugfix).
// ---------------------------------------------------------------------------
__device__ __forceinline__ void attn_tile(
    const float* __restrict__ ks, const float* __restrict__ vs,
    const float* __restrict__ kns,
    const ull* __restrict__ q2, ull* __restrict__ o2,
    float qn, float c, float beta2, float& l,
    int t0, int row, bool domask)
{
    for (int m = 0; m < KT; m++) {
        const longlong2* kr = (const longlong2*)(ks + m * DH_);   // 16 entries
        ull a0 = 0ull, a1 = 0ull, a2 = 0ull, a3 = 0ull;
#pragma unroll
        for (int i = 0; i < 16; i += 2) {
            longlong2 t0v = kr[i];
            longlong2 t1v = kr[i + 1];
            F2FMA(a0, q2[2*i + 0], (ull)t0v.x, a0);
            F2FMA(a1, q2[2*i + 1], (ull)t0v.y, a1);
            F2FMA(a2, q2[2*i + 2], (ull)t1v.x, a2);
            F2FMA(a3, q2[2*i + 3], (ull)t1v.y, a3);
        }
        ull s01, s23, sall;
        F2ADD(s01, a0, a1);
        F2ADD(s23, a2, a3);
        F2ADD(sall, s01, s23);
        float dlo, dhi; F2UNPACK(dlo, dhi, sall);
        float dot = dlo + dhi;

        float kn   = kns[m];
        float ns   = qn + kn;
        float diff = fmaxf(fmaf(dot, -2.f, ns), 0.f);
        float arg  = diff + 1e-8f;
        float ed   = sqrt_apx(arg);
        float cns  = c * ns;
        float one  = 1.f + cns;

        float d_std = sqrt_apx(arg * one);                       // ed*sqrt(1+cns)
        float t1 = fmaf(0.5f, cns, 1.f);
        float t2 = fmaf(0.125f * cns, cns, t1);
        float d_tay = ed * t2;
        float lg = lg2_apx(ed);
        float d_asy = fmaf(0.69314718f, lg, 0.693f);
        d_asy = fmaf(0.25f, cns, d_asy);

        float dist = (ed < 0.1f) ? d_tay : ((ed > 2.0f) ? d_asy : d_std);
        float sc = -beta2 * dist;                                // log2-domain
        if (domask && (t0 + m > row)) sc = -1000.f;
        float p = ex2_apx(sc);
        l += p;
        ull p2; F2PACK(p2, p, p);

        const longlong2* vr = (const longlong2*)(vs + m * DH_);   // 16 entries
#pragma unroll
        for (int i = 0; i < 16; i++) {
            longlong2 t = vr[i];
            F2FMA(o2[2*i + 0], p2, (ull)t.x, o2[2*i + 0]);
            F2FMA(o2[2*i + 1], p2, (ull)t.y, o2[2*i + 1]);
        }
    }
}

// ---------------------------------------------------------------------------
// Hyperbolic flash attention, fp32 + FFMA2.
// grid = (N/QB, B*H), block = QB threads. Thread t owns q-row r0+t.
// ---------------------------------------------------------------------------
__global__ __launch_bounds__(QB)
void hyp_attn(const float* __restrict__ qp, const float* __restrict__ kp,
              const float* __restrict__ vp, const float* __restrict__ knp,
              float* __restrict__ ctx,
              const float* __restrict__ logc_p, const float* __restrict__ logb_p)
{
    __shared__ float ks[KT * DH_];
    __shared__ float vs[KT * DH_];
    __shared__ float kns[KT];

    const int tid = threadIdx.x;
    const int bh  = blockIdx.y;
    const int qb  = (gridDim.x - 1) - blockIdx.x;   // heavy blocks first
    const int r0  = qb * QB;
    const int row = r0 + tid;

    const float c     = softplusf(*logc_p);
    const float beta  = softplusf(*logb_p) + 0.5f;
    const float beta2 = beta * 1.44269504f;         // fold log2(e)

    // Q row packed into 32 f32x2 registers; qn computed on the fly.
    ull q2[32];
    float qn = 0.f;
    {
        const longlong2* qg = (const longlong2*)(qp + ((size_t)bh * N_ + row) * DH_);
#pragma unroll
        for (int i = 0; i < 16; i++) {
            longlong2 t = qg[i];
            q2[2*i]     = (ull)t.x;
            q2[2*i + 1] = (ull)t.y;
            float x0, x1, x2, x3;
            F2UNPACK(x0, x1, (ull)t.x);
            F2UNPACK(x2, x3, (ull)t.y);
            qn = fmaf(x0, x0, qn); qn = fmaf(x1, x1, qn);
            qn = fmaf(x2, x2, qn); qn = fmaf(x3, x3, qn);
        }
    }

    ull o2[32];
#pragma unroll
    for (int i = 0; i < 32; i++) o2[i] = 0ull;
    float l = 0.f;

    const int fullTiles = 2 * qb;       // tiles with no causal masking
    for (int T = 0; T < fullTiles + 2; T++) {
        const int t0 = T * KT;
        __syncthreads();
        {
            const float4* k4 = (const float4*)(kp + ((size_t)bh * N_ + t0) * DH_);
            const float4* v4 = (const float4*)(vp + ((size_t)bh * N_ + t0) * DH_);
            float4* ksd = (float4*)ks;
            float4* vsd = (float4*)vs;
#pragma unroll
            for (int i = 0; i < 8; i++) {
                int f = i * QB + tid;
                ksd[f] = k4[f];
                vsd[f] = v4[f];
            }
            if (tid < KT) kns[tid] = knp[bh * N_ + t0 + tid];
        }
        __syncthreads();

        if (T < fullTiles)
            attn_tile(ks, vs, kns, q2, o2, qn, c, beta2, l, t0, row, false);
        else
            attn_tile(ks, vs, kns, q2, o2, qn, c, beta2, l, t0, row, true);
    }

    // Write ctx[(b*N + row)*D + h*64 + d]
    const float inv = 1.f / l;
    const int b = bh >> 4, h = bh & 15;
    float* outp = ctx + ((size_t)b * N_ + row) * D_ + h * DH_;
#pragma unroll
    for (int i = 0; i < 16; i++) {
        float x0, x1, x2, x3;
        F2UNPACK(x0, x1, o2[2*i]);
        F2UNPACK(x2, x3, o2[2*i + 1]);
        float4 val = make_float4(x0 * inv, x1 * inv, x2 * inv, x3 * inv);
        *(float4*)(outp + i * 4) = val;
    }
}

// ---------------------------------------------------------------------------
extern "C" void kernel_launch(void* const* d_in, const int* in_sizes, int n_in,
                              void* d_out, int out_size)
{
    const float* x     = (const float*)d_in[0];
    const float* Wq    = (const float*)d_in[1];
    const float* Wk    = (const float*)d_in[2];
    const float* Wv    = (const float*)d_in[3];
    const float* Wo    = (const float*)d_in[4];
    const float* log_c = (const float*)d_in[5];
    const float* log_b = (const float*)d_in[6];
    float* out = (float*)d_out;

    float *qptr, *kptr, *vptr, *ctxptr, *knp;
    cudaGetSymbolAddress((void**)&qptr,  g_q);
    cudaGetSymbolAddress((void**)&kptr,  g_k);
    cudaGetSymbolAddress((void**)&vptr,  g_v);
    cudaGetSymbolAddress((void**)&ctxptr, g_ctx);
    cudaGetSymbolAddress((void**)&knp,   g_kn);

    // QKV projections (fused into one launch via z)
    dim3 gq(D_ / 128, ROWS_ / 128, 3);
    sgemm_xwt<<<gq, 256>>>(x, Wq, Wk, Wv, qptr, kptr, vptr, 1);

    // K norms
    k_norms<<<BHN_ / 8, 256>>>(kptr, knp);

    // Attention
    hyp_attn<<<dim3(N_ / QB, B_ * H_), QB>>>(qptr, kptr, vptr, knp, ctxptr,
                                             log_c, log_b);

    // Output projection
    dim3 go(D_ / 128, ROWS_ / 128, 1);
    sgemm_xwt<<<go, 256>>>(ctxptr, Wo, Wo, Wo, out, out, out, 0);
}

// round 12
// speedup vs baseline: 1.7455x; 1.4144x over previous
#include <cuda_runtime.h>
#include <cuda_bf16.h>
#include <math.h>
#include <cstdint>

// Problem constants
#define B_  2
#define N_  2048
#define D_  1024
#define H_  16
#define DH_ 64
#define ROWS_ (B_*N_)          // 4096
#define BHN_  (B_*H_*N_)       // 65536

#define QB 128   // q rows per attention CTA (1 thread per row)
#define KT 64    // key tile

typedef unsigned long long ull;

// ---------------------------------------------------------------------------
// packed fp32x2 + MUFU approx helpers (sm_103a)
// ---------------------------------------------------------------------------
#define F2FMA(d, a, b, c) \
    asm("fma.rn.f32x2 %0, %1, %2, %3;" : "=l"(d) : "l"(a), "l"(b), "l"(c))
#define F2ADD(d, a, b) \
    asm("add.rn.f32x2 %0, %1, %2;" : "=l"(d) : "l"(a), "l"(b))
#define F2PACK(d, lo, hi) \
    asm("mov.b64 %0, {%1, %2};" : "=l"(d) : "r"(__float_as_uint(lo)), "r"(__float_as_uint(hi)))
#define F2UNPACK(lo, hi, v) do { unsigned _ulo, _uhi; \
    asm("mov.b64 {%0, %1}, %2;" : "=r"(_ulo), "=r"(_uhi) : "l"(v)); \
    lo = __uint_as_float(_ulo); hi = __uint_as_float(_uhi); } while (0)
__device__ __forceinline__ float sqrt_apx(float x) {
    float r; asm("sqrt.approx.f32 %0, %1;" : "=f"(r) : "f"(x)); return r;
}
__device__ __forceinline__ float lg2_apx(float x) {
    float r; asm("lg2.approx.f32 %0, %1;" : "=f"(r) : "f"(x)); return r;
}
__device__ __forceinline__ float ex2_apx(float x) {
    float r; asm("ex2.approx.f32 %0, %1;" : "=f"(r) : "f"(x)); return r;
}

// ---------------------------------------------------------------------------
// ldmatrix + mma.sync helpers (baseline PTX — no 'a' arch features)
// ---------------------------------------------------------------------------
__device__ __forceinline__ uint32_t smem_u32(const void* p) {
    uint32_t a;
    asm("{ .reg .u64 t; cvta.to.shared.u64 t, %1; cvt.u32.u64 %0, t; }" : "=r"(a) : "l"(p));
    return a;
}
#define LDSM_X4(r, addr) \
    asm volatile("ldmatrix.sync.aligned.m8n8.x4.shared.b16 {%0,%1,%2,%3}, [%4];" \
        : "=r"((r)[0]), "=r"((r)[1]), "=r"((r)[2]), "=r"((r)[3]) : "r"(addr))
#define MMA_BF16(d, a, b0v, b1v) \
    asm volatile("mma.sync.aligned.m16n8k16.row.col.f32.bf16.bf16.f32 " \
        "{%0,%1,%2,%3}, {%4,%5,%6,%7}, {%8,%9}, {%0,%1,%2,%3};" \
        : "+f"((d)[0]), "+f"((d)[1]), "+f"((d)[2]), "+f"((d)[3]) \
        : "r"((a)[0]), "r"((a)[1]), "r"((a)[2]), "r"((a)[3]), "r"(b0v), "r"(b1v))

// ---------------------------------------------------------------------------
// Scratch (static device globals — no allocation)
// ---------------------------------------------------------------------------
__device__ float g_q[B_*H_*N_*DH_];
__device__ float g_k[B_*H_*N_*DH_];
__device__ float g_v[B_*H_*N_*DH_];
__device__ float g_ctx[B_*N_*D_];
__device__ float g_kn[BHN_];
__device__ __nv_bfloat16 g_xh[ROWS_*D_],  g_xl[ROWS_*D_];
__device__ __nv_bfloat16 g_wqh[D_*D_], g_wql[D_*D_];
__device__ __nv_bfloat16 g_wkh[D_*D_], g_wkl[D_*D_];
__device__ __nv_bfloat16 g_wvh[D_*D_], g_wvl[D_*D_];
__device__ __nv_bfloat16 g_woh[D_*D_], g_wol[D_*D_];
__device__ __nv_bfloat16 g_cth[ROWS_*D_], g_ctl[ROWS_*D_];

__device__ __forceinline__ float softplusf(float x) {
    return (x > 20.f) ? x : log1pf(__expf(x));
}

// ---------------------------------------------------------------------------
// fp32 -> (bf16 hi, bf16 lo) split, 4 elements/thread
// ---------------------------------------------------------------------------
__global__ void split_bf16(const float* __restrict__ s,
                           __nv_bfloat16* __restrict__ h,
                           __nv_bfloat16* __restrict__ l, int n4)
{
    int i = blockIdx.x * blockDim.x + threadIdx.x;
    if (i >= n4) return;
    float4 v = ((const float4*)s)[i];
    __nv_bfloat16 h0 = __float2bfloat16(v.x), h1 = __float2bfloat16(v.y);
    __nv_bfloat16 h2 = __float2bfloat16(v.z), h3 = __float2bfloat16(v.w);
    __nv_bfloat16 l0 = __float2bfloat16(v.x - __bfloat162float(h0));
    __nv_bfloat16 l1 = __float2bfloat16(v.y - __bfloat162float(h1));
    __nv_bfloat16 l2 = __float2bfloat16(v.z - __bfloat162float(h2));
    __nv_bfloat16 l3 = __float2bfloat16(v.w - __bfloat162float(h3));
    ushort4 hv = make_ushort4(__bfloat16_as_ushort(h0), __bfloat16_as_ushort(h1),
                              __bfloat16_as_ushort(h2), __bfloat16_as_ushort(h3));
    ushort4 lv = make_ushort4(__bfloat16_as_ushort(l0), __bfloat16_as_ushort(l1),
                              __bfloat16_as_ushort(l2), __bfloat16_as_ushort(l3));
    ((ushort4*)h)[i] = hv;
    ((ushort4*)l)[i] = lv;
}

// ---------------------------------------------------------------------------
// bf16-split HMMA GEMM: C = A @ W^T (fp32) via Ah·Bh + Ah·Bl + Al·Bh.
// mma.sync.m16n8k16 bf16, fp32 accum. Tile 128x64x32, 256 thr (8 warps 4Mx2N).
// SMEM rows padded to 80 B (conflict-free ldmatrix phases).
// ---------------------------------------------------------------------------
#define GST 40   // smem row stride in bf16 elements (80 B)

__global__ __launch_bounds__(256)
void gemm_tc(const __nv_bfloat16* __restrict__ Ah, const __nv_bfloat16* __restrict__ Al,
             const __nv_bfloat16* __restrict__ Bh0, const __nv_bfloat16* __restrict__ Bl0,
             const __nv_bfloat16* __restrict__ Bh1, const __nv_bfloat16* __restrict__ Bl1,
             const __nv_bfloat16* __restrict__ Bh2, const __nv_bfloat16* __restrict__ Bl2,
             float* __restrict__ C0, float* __restrict__ C1, float* __restrict__ C2,
             int headLayout)
{
    __shared__ __align__(16) __nv_bfloat16 sAh[128*GST], sAl[128*GST];
    __shared__ __align__(16) __nv_bfloat16 sBh[64*GST],  sBl[64*GST];

    const int z = blockIdx.z;
    const __nv_bfloat16* __restrict__ Bh = (z == 0) ? Bh0 : (z == 1) ? Bh1 : Bh2;
    const __nv_bfloat16* __restrict__ Bl = (z == 0) ? Bl0 : (z == 1) ? Bl1 : Bl2;
    float* __restrict__ C = (z == 0) ? C0 : (z == 1) ? C1 : C2;

    const int tid  = threadIdx.x;
    const int lane = tid & 31;
    const int wid  = tid >> 5;
    const int wm   = wid & 3;        // 0..3 -> M
    const int wn   = wid >> 2;       // 0..1 -> N
    const int rowBase = blockIdx.y * 128;
    const int colBase = blockIdx.x * 64;

    const uint32_t uAh = smem_u32(sAh), uAl = smem_u32(sAl);
    const uint32_t uBh = smem_u32(sBh), uBl = smem_u32(sBl);

    // ldmatrix lane base offsets (bytes)
    const uint32_t aBase = (uint32_t)((wm * 32 + (lane & 15)) * 80 + (lane >> 4) * 16);
    const uint32_t bBase = (uint32_t)((wn * 32 + ((lane >> 4) & 1) * 8 + (lane & 7)) * 80
                                      + ((lane >> 3) & 1) * 16);

    float acc[2][4][4];
#pragma unroll
    for (int mf = 0; mf < 2; mf++)
#pragma unroll
        for (int nf = 0; nf < 4; nf++)
#pragma unroll
            for (int r = 0; r < 4; r++) acc[mf][nf][r] = 0.f;

    for (int kk = 0; kk < D_; kk += 32) {
        // A tiles: 128 rows x 4 chunks(16B) per matrix; 2 chunks/thread
#pragma unroll
        for (int i = 0; i < 2; i++) {
            int idx = tid + i * 256;
            int r = idx >> 2, c = idx & 3;
            size_t g = (size_t)(rowBase + r) * D_ + kk + c * 8;
            *(uint4*)((char*)sAh + r * 80 + c * 16) = *(const uint4*)(Ah + g);
            *(uint4*)((char*)sAl + r * 80 + c * 16) = *(const uint4*)(Al + g);
        }
        // B tiles: 64 rows x 4 chunks; 1 chunk/thread
        {
            int r = tid >> 2, c = tid & 3;
            size_t g = (size_t)(colBase + r) * D_ + kk + c * 8;
            *(uint4*)((char*)sBh + r * 80 + c * 16) = *(const uint4*)(Bh + g);
            *(uint4*)((char*)sBl + r * 80 + c * 16) = *(const uint4*)(Bl + g);
        }
        __syncthreads();

#pragma unroll
        for (int k16 = 0; k16 < 2; k16++) {
            uint32_t ah[2][4], al[2][4], bh[2][4], bl[2][4];
#pragma unroll
            for (int mf = 0; mf < 2; mf++) {
                LDSM_X4(ah[mf], uAh + aBase + mf * 1280 + k16 * 32);
                LDSM_X4(al[mf], uAl + aBase + mf * 1280 + k16 * 32);
            }
#pragma unroll
            for (int n16 = 0; n16 < 2; n16++) {
                LDSM_X4(bh[n16], uBh + bBase + n16 * 1280 + k16 * 32);
                LDSM_X4(bl[n16], uBl + bBase + n16 * 1280 + k16 * 32);
            }
#pragma unroll
            for (int mf = 0; mf < 2; mf++)
#pragma unroll
                for (int nf = 0; nf < 4; nf++) {
                    const int n16 = nf >> 1, pr = (nf & 1) * 2;
                    MMA_BF16(acc[mf][nf], ah[mf], bh[n16][pr], bh[n16][pr + 1]);
                    MMA_BF16(acc[mf][nf], ah[mf], bl[n16][pr], bl[n16][pr + 1]);
                    MMA_BF16(acc[mf][nf], al[mf], bh[n16][pr], bh[n16][pr + 1]);
                }
        }
        __syncthreads();
    }

    // Epilogue: lane (groupid, tid4) owns rows g,g+8 and cols 2*tid4,+1 per frag
    const int gi = lane >> 2, t4 = lane & 3;
#pragma unroll
    for (int mf = 0; mf < 2; mf++) {
#pragma unroll
        for (int nf = 0; nf < 4; nf++) {
            int col = colBase + wn * 32 + nf * 8 + t4 * 2;
            int row0 = rowBase + wm * 32 + mf * 16 + gi;
            int row1 = row0 + 8;
            float2 v01 = make_float2(acc[mf][nf][0], acc[mf][nf][1]);
            float2 v23 = make_float2(acc[mf][nf][2], acc[mf][nf][3]);
            if (headLayout) {
                int h = col >> 6, dh = col & 63;
                int b0 = row0 >> 11, n0 = row0 & 2047;
                int b1 = row1 >> 11, n1 = row1 & 2047;
                *(float2*)(C + (((size_t)(b0 * H_ + h)) * N_ + n0) * DH_ + dh) = v01;
                *(float2*)(C + (((size_t)(b1 * H_ + h)) * N_ + n1) * DH_ + dh) = v23;
            } else {
                *(float2*)(C + (size_t)row0 * D_ + col) = v01;
                *(float2*)(C + (size_t)row1 * D_ + col) = v23;
            }
        }
    }
}

// ---------------------------------------------------------------------------
// K row squared-norms: one warp per 64-elem row.
// ---------------------------------------------------------------------------
__global__ void k_norms(const float* __restrict__ k, float* __restrict__ kn)
{
    int gw = (blockIdx.x * blockDim.x + threadIdx.x) >> 5;
    int lane = threadIdx.x & 31;
    if (gw >= BHN_) return;
    const float* r = k + (size_t)gw * DH_;
    float a = r[lane], b = r[lane + 32];
    float s = a * a + b * b;
#pragma unroll
    for (int off = 16; off > 0; off >>= 1)
        s += __shfl_xor_sync(0xFFFFFFFFu, s, off);
    if (lane == 0) kn[gw] = s;
}

// ---------------------------------------------------------------------------
// One KT-key tile of hyperbolic attention for one q-row (held in q2/o2).
// ---------------------------------------------------------------------------
__device__ __forceinline__ void attn_tile(
    const float* __restrict__ ks, const float* __restrict__ vs,
    const float* __restrict__ kns,
    const ull* __restrict__ q2, ull* __restrict__ o2,
    float qn, float c, float beta2, float& l,
    int t0, int row, bool domask)
{
    for (int m = 0; m < KT; m++) {
        const longlong2* kr = (const longlong2*)(ks + m * DH_);   // 16 entries
        ull a0 = 0ull, a1 = 0ull, a2 = 0ull, a3 = 0ull;
#pragma unroll
        for (int i = 0; i < 16; i += 2) {
            longlong2 t0v = kr[i];
            longlong2 t1v = kr[i + 1];
            F2FMA(a0, q2[2*i + 0], (ull)t0v.x, a0);
            F2FMA(a1, q2[2*i + 1], (ull)t0v.y, a1);
            F2FMA(a2, q2[2*i + 2], (ull)t1v.x, a2);
            F2FMA(a3, q2[2*i + 3], (ull)t1v.y, a3);
        }
        ull s01, s23, sall;
        F2ADD(s01, a0, a1);
        F2ADD(s23, a2, a3);
        F2ADD(sall, s01, s23);
        float dlo, dhi; F2UNPACK(dlo, dhi, sall);
        float dot = dlo + dhi;

        float kn   = kns[m];
        float ns   = qn + kn;
        float diff = fmaxf(fmaf(dot, -2.f, ns), 0.f);
        float arg  = diff + 1e-8f;
        float ed   = sqrt_apx(arg);
        float cns  = c * ns;
        float one  = 1.f + cns;

        float d_std = sqrt_apx(arg * one);
        float t1 = fmaf(0.5f, cns, 1.f);
        float t2 = fmaf(0.125f * cns, cns, t1);
        float d_tay = ed * t2;
        float lg = lg2_apx(ed);
        float d_asy = fmaf(0.69314718f, lg, 0.693f);
        d_asy = fmaf(0.25f, cns, d_asy);

        float dist = (ed < 0.1f) ? d_tay : ((ed > 2.0f) ? d_asy : d_std);
        float sc = -beta2 * dist;
        if (domask && (t0 + m > row)) sc = -1000.f;
        float p = ex2_apx(sc);
        l += p;
        ull p2; F2PACK(p2, p, p);

        const longlong2* vr = (const longlong2*)(vs + m * DH_);   // 16 entries
#pragma unroll
        for (int i = 0; i < 16; i++) {
            longlong2 t = vr[i];
            F2FMA(o2[2*i + 0], p2, (ull)t.x, o2[2*i + 0]);
            F2FMA(o2[2*i + 1], p2, (ull)t.y, o2[2*i + 1]);
        }
    }
}

// ---------------------------------------------------------------------------
// Hyperbolic flash attention, fp32 + FFMA2.
// ---------------------------------------------------------------------------
__global__ __launch_bounds__(QB)
void hyp_attn(const float* __restrict__ qp, const float* __restrict__ kp,
              const float* __restrict__ vp, const float* __restrict__ knp,
              float* __restrict__ ctx,
              const float* __restrict__ logc_p, const float* __restrict__ logb_p)
{
    __shared__ float ks[KT * DH_];
    __shared__ float vs[KT * DH_];
    __shared__ float kns[KT];

    const int tid = threadIdx.x;
    const int bh  = blockIdx.y;
    const int qb  = (gridDim.x - 1) - blockIdx.x;
    const int r0  = qb * QB;
    const int row = r0 + tid;

    const float c     = softplusf(*logc_p);
    const float beta  = softplusf(*logb_p) + 0.5f;
    const float beta2 = beta * 1.44269504f;

    ull q2[32];
    float qn = 0.f;
    {
        const longlong2* qg = (const longlong2*)(qp + ((size_t)bh * N_ + row) * DH_);
#pragma unroll
        for (int i = 0; i < 16; i++) {
            longlong2 t = qg[i];
            q2[2*i]     = (ull)t.x;
            q2[2*i + 1] = (ull)t.y;
            float x0, x1, x2, x3;
            F2UNPACK(x0, x1, (ull)t.x);
            F2UNPACK(x2, x3, (ull)t.y);
            qn = fmaf(x0, x0, qn); qn = fmaf(x1, x1, qn);
            qn = fmaf(x2, x2, qn); qn = fmaf(x3, x3, qn);
        }
    }

    ull o2[32];
#pragma unroll
    for (int i = 0; i < 32; i++) o2[i] = 0ull;
    float l = 0.f;

    const int fullTiles = 2 * qb;
    for (int T = 0; T < fullTiles + 2; T++) {
        const int t0 = T * KT;
        __syncthreads();
        {
            const float4* k4 = (const float4*)(kp + ((size_t)bh * N_ + t0) * DH_);
            const float4* v4 = (const float4*)(vp + ((size_t)bh * N_ + t0) * DH_);
            float4* ksd = (float4*)ks;
            float4* vsd = (float4*)vs;
#pragma unroll
            for (int i = 0; i < 8; i++) {
                int f = i * QB + tid;
                ksd[f] = k4[f];
                vsd[f] = v4[f];
            }
            if (tid < KT) kns[tid] = knp[bh * N_ + t0 + tid];
        }
        __syncthreads();

        if (T < fullTiles)
            attn_tile(ks, vs, kns, q2, o2, qn, c, beta2, l, t0, row, false);
        else
            attn_tile(ks, vs, kns, q2, o2, qn, c, beta2, l, t0, row, true);
    }

    const float inv = 1.f / l;
    const int b = bh >> 4, h = bh & 15;
    float* outp = ctx + ((size_t)b * N_ + row) * D_ + h * DH_;
#pragma unroll
    for (int i = 0; i < 16; i++) {
        float x0, x1, x2, x3;
        F2UNPACK(x0, x1, o2[2*i]);
        F2UNPACK(x2, x3, o2[2*i + 1]);
        float4 val = make_float4(x0 * inv, x1 * inv, x2 * inv, x3 * inv);
        *(float4*)(outp + i * 4) = val;
    }
}

// ---------------------------------------------------------------------------
extern "C" void kernel_launch(void* const* d_in, const int* in_sizes, int n_in,
                              void* d_out, int out_size)
{
    const float* x     = (const float*)d_in[0];
    const float* Wq    = (const float*)d_in[1];
    const float* Wk    = (const float*)d_in[2];
    const float* Wv    = (const float*)d_in[3];
    const float* Wo    = (const float*)d_in[4];
    const float* log_c = (const float*)d_in[5];
    const float* log_b = (const float*)d_in[6];
    float* out = (float*)d_out;

    float *qptr, *kptr, *vptr, *ctxptr, *knp;
    cudaGetSymbolAddress((void**)&qptr,   g_q);
    cudaGetSymbolAddress((void**)&kptr,   g_k);
    cudaGetSymbolAddress((void**)&vptr,   g_v);
    cudaGetSymbolAddress((void**)&ctxptr, g_ctx);
    cudaGetSymbolAddress((void**)&knp,    g_kn);

    __nv_bfloat16 *xh, *xl, *wqh, *wql, *wkh, *wkl, *wvh, *wvl, *woh, *wol, *cth, *ctl;
    cudaGetSymbolAddress((void**)&xh,  g_xh);  cudaGetSymbolAddress((void**)&xl,  g_xl);
    cudaGetSymbolAddress((void**)&wqh, g_wqh); cudaGetSymbolAddress((void**)&wql, g_wql);
    cudaGetSymbolAddress((void**)&wkh, g_wkh); cudaGetSymbolAddress((void**)&wkl, g_wkl);
    cudaGetSymbolAddress((void**)&wvh, g_wvh); cudaGetSymbolAddress((void**)&wvl, g_wvl);
    cudaGetSymbolAddress((void**)&woh, g_woh); cudaGetSymbolAddress((void**)&wol, g_wol);
    cudaGetSymbolAddress((void**)&cth, g_cth); cudaGetSymbolAddress((void**)&ctl, g_ctl);

    // Split inputs to bf16 hi/lo
    const int n4x = ROWS_ * D_ / 4;   // 1,048,576
    const int n4w = D_ * D_ / 4;      // 262,144
    split_bf16<<<n4x / 256, 256>>>(x,  xh,  xl,  n4x);
    split_bf16<<<n4w / 256, 256>>>(Wq, wqh, wql, n4w);
    split_bf16<<<n4w / 256, 256>>>(Wk, wkh, wkl, n4w);
    split_bf16<<<n4w / 256, 256>>>(Wv, wvh, wvl, n4w);
    split_bf16<<<n4w / 256, 256>>>(Wo, woh, wol, n4w);

    // QKV projections via HMMA (z selects weight/output)
    gemm_tc<<<dim3(D_ / 64, ROWS_ / 128, 3), 256>>>(
        xh, xl, wqh, wql, wkh, wkl, wvh, wvl, qptr, kptr, vptr, 1);

    // K norms
    k_norms<<<BHN_ / 8, 256>>>(kptr, knp);

    // Attention
    hyp_attn<<<dim3(N_ / QB, B_ * H_), QB>>>(qptr, kptr, vptr, knp, ctxptr,
                                             log_c, log_b);

    // Split ctx, then output projection
    split_bf16<<<n4x / 256, 256>>>(ctxptr, cth, ctl, n4x);
    gemm_tc<<<dim3(D_ / 64, ROWS_ / 128, 1), 256>>>(
        cth, ctl, woh, wol, woh, wol, woh, wol, out, out, out, 0);
}

// round 13
// speedup vs baseline: 2.6849x; 1.5382x over previous
#include <cuda_runtime.h>
#include <cuda_bf16.h>
#include <math.h>
#include <cstdint>

// Problem constants
#define B_  2
#define N_  2048
#define D_  1024
#define H_  16
#define DH_ 64
#define ROWS_ (B_*N_)          // 4096
#define BHN_  (B_*H_*N_)       // 65536

// ---------------------------------------------------------------------------
// MUFU approx helpers
// ---------------------------------------------------------------------------
__device__ __forceinline__ float sqrt_apx(float x) {
    float r; asm("sqrt.approx.f32 %0, %1;" : "=f"(r) : "f"(x)); return r;
}
__device__ __forceinline__ float lg2_apx(float x) {
    float r; asm("lg2.approx.f32 %0, %1;" : "=f"(r) : "f"(x)); return r;
}
__device__ __forceinline__ float ex2_apx(float x) {
    float r; asm("ex2.approx.f32 %0, %1;" : "=f"(r) : "f"(x)); return r;
}

// ---------------------------------------------------------------------------
// ldmatrix + mma.sync helpers (baseline PTX — no 'a' arch features)
// ---------------------------------------------------------------------------
__device__ __forceinline__ uint32_t smem_u32(const void* p) {
    uint32_t a;
    asm("{ .reg .u64 t; cvta.to.shared.u64 t, %1; cvt.u32.u64 %0, t; }" : "=r"(a) : "l"(p));
    return a;
}
#define LDSM_X4(r, addr) \
    asm volatile("ldmatrix.sync.aligned.m8n8.x4.shared.b16 {%0,%1,%2,%3}, [%4];" \
        : "=r"((r)[0]), "=r"((r)[1]), "=r"((r)[2]), "=r"((r)[3]) : "r"(addr))
#define MMA_BF16(d, a, b0v, b1v) \
    asm volatile("mma.sync.aligned.m16n8k16.row.col.f32.bf16.bf16.f32 " \
        "{%0,%1,%2,%3}, {%4,%5,%6,%7}, {%8,%9}, {%0,%1,%2,%3};" \
        : "+f"((d)[0]), "+f"((d)[1]), "+f"((d)[2]), "+f"((d)[3]) \
        : "r"((a)[0]), "r"((a)[1]), "r"((a)[2]), "r"((a)[3]), "r"(b0v), "r"(b1v))
// pack (lo=p0, hi=p1) into bf16x2
#define CVTPK(d, p0, p1) \
    asm("cvt.rn.bf16x2.f32 %0, %1, %2;" : "=r"(d) : "f"(p1), "f"(p0))

// ---------------------------------------------------------------------------
// Scratch (static device globals — no allocation)
// ---------------------------------------------------------------------------
__device__ float g_q[BHN_*DH_];
__device__ float g_k[BHN_*DH_];
__device__ float g_v[BHN_*DH_];
__device__ float g_ctx[ROWS_*D_];
__device__ float g_kn[BHN_];
__device__ float g_qn[BHN_];
__device__ __nv_bfloat16 g_xh[ROWS_*D_],  g_xl[ROWS_*D_];
__device__ __nv_bfloat16 g_wqh[D_*D_], g_wql[D_*D_];
__device__ __nv_bfloat16 g_wkh[D_*D_], g_wkl[D_*D_];
__device__ __nv_bfloat16 g_wvh[D_*D_], g_wvl[D_*D_];
__device__ __nv_bfloat16 g_woh[D_*D_], g_wol[D_*D_];
__device__ __nv_bfloat16 g_cth[ROWS_*D_], g_ctl[ROWS_*D_];
__device__ __nv_bfloat16 g_qh[BHN_*DH_], g_ql[BHN_*DH_];
__device__ __nv_bfloat16 g_kh[BHN_*DH_], g_kl[BHN_*DH_];
__device__ __nv_bfloat16 g_vh[BHN_*DH_], g_vl[BHN_*DH_];

__device__ __forceinline__ float softplusf(float x) {
    return (x > 20.f) ? x : log1pf(__expf(x));
}

// ---------------------------------------------------------------------------
// fp32 -> (bf16 hi, bf16 lo) split, 4 elements/thread
// ---------------------------------------------------------------------------
__global__ void split_bf16(const float* __restrict__ s,
                           __nv_bfloat16* __restrict__ h,
                           __nv_bfloat16* __restrict__ l, int n4)
{
    int i = blockIdx.x * blockDim.x + threadIdx.x;
    if (i >= n4) return;
    float4 v = ((const float4*)s)[i];
    __nv_bfloat16 h0 = __float2bfloat16(v.x), h1 = __float2bfloat16(v.y);
    __nv_bfloat16 h2 = __float2bfloat16(v.z), h3 = __float2bfloat16(v.w);
    __nv_bfloat16 l0 = __float2bfloat16(v.x - __bfloat162float(h0));
    __nv_bfloat16 l1 = __float2bfloat16(v.y - __bfloat162float(h1));
    __nv_bfloat16 l2 = __float2bfloat16(v.z - __bfloat162float(h2));
    __nv_bfloat16 l3 = __float2bfloat16(v.w - __bfloat162float(h3));
    ushort4 hv = make_ushort4(__bfloat16_as_ushort(h0), __bfloat16_as_ushort(h1),
                              __bfloat16_as_ushort(h2), __bfloat16_as_ushort(h3));
    ushort4 lv = make_ushort4(__bfloat16_as_ushort(l0), __bfloat16_as_ushort(l1),
                              __bfloat16_as_ushort(l2), __bfloat16_as_ushort(l3));
    ((ushort4*)h)[i] = hv;
    ((ushort4*)l)[i] = lv;
}

// ---------------------------------------------------------------------------
// bf16-split HMMA GEMM (unchanged from R12 — passed at rel_err 1.8e-5)
// ---------------------------------------------------------------------------
#define GST 40   // smem row stride in bf16 elements (80 B)

__global__ __launch_bounds__(256)
void gemm_tc(const __nv_bfloat16* __restrict__ Ah, const __nv_bfloat16* __restrict__ Al,
             const __nv_bfloat16* __restrict__ Bh0, const __nv_bfloat16* __restrict__ Bl0,
             const __nv_bfloat16* __restrict__ Bh1, const __nv_bfloat16* __restrict__ Bl1,
             const __nv_bfloat16* __restrict__ Bh2, const __nv_bfloat16* __restrict__ Bl2,
             float* __restrict__ C0, float* __restrict__ C1, float* __restrict__ C2,
             int headLayout)
{
    __shared__ __align__(16) __nv_bfloat16 sAh[128*GST], sAl[128*GST];
    __shared__ __align__(16) __nv_bfloat16 sBh[64*GST],  sBl[64*GST];

    const int z = blockIdx.z;
    const __nv_bfloat16* __restrict__ Bh = (z == 0) ? Bh0 : (z == 1) ? Bh1 : Bh2;
    const __nv_bfloat16* __restrict__ Bl = (z == 0) ? Bl0 : (z == 1) ? Bl1 : Bl2;
    float* __restrict__ C = (z == 0) ? C0 : (z == 1) ? C1 : C2;

    const int tid  = threadIdx.x;
    const int lane = tid & 31;
    const int wid  = tid >> 5;
    const int wm   = wid & 3;
    const int wn   = wid >> 2;
    const int rowBase = blockIdx.y * 128;
    const int colBase = blockIdx.x * 64;

    const uint32_t uAh = smem_u32(sAh), uAl = smem_u32(sAl);
    const uint32_t uBh = smem_u32(sBh), uBl = smem_u32(sBl);

    const uint32_t aBase = (uint32_t)((wm * 32 + (lane & 15)) * 80 + (lane >> 4) * 16);
    const uint32_t bBase = (uint32_t)((wn * 32 + ((lane >> 4) & 1) * 8 + (lane & 7)) * 80
                                      + ((lane >> 3) & 1) * 16);

    float acc[2][4][4];
#pragma unroll
    for (int mf = 0; mf < 2; mf++)
#pragma unroll
        for (int nf = 0; nf < 4; nf++)
#pragma unroll
            for (int r = 0; r < 4; r++) acc[mf][nf][r] = 0.f;

    for (int kk = 0; kk < D_; kk += 32) {
#pragma unroll
        for (int i = 0; i < 2; i++) {
            int idx = tid + i * 256;
            int r = idx >> 2, c = idx & 3;
            size_t g = (size_t)(rowBase + r) * D_ + kk + c * 8;
            *(uint4*)((char*)sAh + r * 80 + c * 16) = *(const uint4*)(Ah + g);
            *(uint4*)((char*)sAl + r * 80 + c * 16) = *(const uint4*)(Al + g);
        }
        {
            int r = tid >> 2, c = tid & 3;
            size_t g = (size_t)(colBase + r) * D_ + kk + c * 8;
            *(uint4*)((char*)sBh + r * 80 + c * 16) = *(const uint4*)(Bh + g);
            *(uint4*)((char*)sBl + r * 80 + c * 16) = *(const uint4*)(Bl + g);
        }
        __syncthreads();

#pragma unroll
        for (int k16 = 0; k16 < 2; k16++) {
            uint32_t ah[2][4], al[2][4], bh[2][4], bl[2][4];
#pragma unroll
            for (int mf = 0; mf < 2; mf++) {
                LDSM_X4(ah[mf], uAh + aBase + mf * 1280 + k16 * 32);
                LDSM_X4(al[mf], uAl + aBase + mf * 1280 + k16 * 32);
            }
#pragma unroll
            for (int n16 = 0; n16 < 2; n16++) {
                LDSM_X4(bh[n16], uBh + bBase + n16 * 1280 + k16 * 32);
                LDSM_X4(bl[n16], uBl + bBase + n16 * 1280 + k16 * 32);
            }
#pragma unroll
            for (int mf = 0; mf < 2; mf++)
#pragma unroll
                for (int nf = 0; nf < 4; nf++) {
                    const int n16 = nf >> 1, pr = (nf & 1) * 2;
                    MMA_BF16(acc[mf][nf], ah[mf], bh[n16][pr], bh[n16][pr + 1]);
                    MMA_BF16(acc[mf][nf], ah[mf], bl[n16][pr], bl[n16][pr + 1]);
                    MMA_BF16(acc[mf][nf], al[mf], bh[n16][pr], bh[n16][pr + 1]);
                }
        }
        __syncthreads();
    }

    const int gi = lane >> 2, t4 = lane & 3;
#pragma unroll
    for (int mf = 0; mf < 2; mf++) {
#pragma unroll
        for (int nf = 0; nf < 4; nf++) {
            int col = colBase + wn * 32 + nf * 8 + t4 * 2;
            int row0 = rowBase + wm * 32 + mf * 16 + gi;
            int row1 = row0 + 8;
            float2 v01 = make_float2(acc[mf][nf][0], acc[mf][nf][1]);
            float2 v23 = make_float2(acc[mf][nf][2], acc[mf][nf][3]);
            if (headLayout) {
                int h = col >> 6, dh = col & 63;
                int b0 = row0 >> 11, n0 = row0 & 2047;
                int b1 = row1 >> 11, n1 = row1 & 2047;
                *(float2*)(C + (((size_t)(b0 * H_ + h)) * N_ + n0) * DH_ + dh) = v01;
                *(float2*)(C + (((size_t)(b1 * H_ + h)) * N_ + n1) * DH_ + dh) = v23;
            } else {
                *(float2*)(C + (size_t)row0 * D_ + col) = v01;
                *(float2*)(C + (size_t)row1 * D_ + col) = v23;
            }
        }
    }
}

// ---------------------------------------------------------------------------
// Row squared-norms: one warp per 64-elem row (used for q and k).
// ---------------------------------------------------------------------------
__global__ void row_norms(const float* __restrict__ src, float* __restrict__ dst)
{
    int gw = (blockIdx.x * blockDim.x + threadIdx.x) >> 5;
    int lane = threadIdx.x & 31;
    if (gw >= BHN_) return;
    const float* r = src + (size_t)gw * DH_;
    float a = r[lane], b = r[lane + 32];
    float s = a * a + b * b;
#pragma unroll
    for (int off = 16; off > 0; off >>= 1)
        s += __shfl_xor_sync(0xFFFFFFFFu, s, off);
    if (lane == 0) dst[gw] = s;
}

// ---------------------------------------------------------------------------
// Tensor-core hyperbolic flash attention.
// Grid (32 qblocks reversed, 32 bh), 128 threads (4 warps, m16 each).
// Q/K split bf16 (3-product S), P/V split bf16 (3-product PV).
// Dynamic smem layout (144B row stride => conflict-free ldmatrix):
// ---------------------------------------------------------------------------
#define AST 144        // bytes per smem row
#define SQH 0
#define SQL (SQH + 64*AST)
#define SKH (SQL + 64*AST)
#define SKL (SKH + 64*AST)
#define SVH (SKL + 64*AST)     // transposed V: rows=dh, cols=key
#define SVL (SVH + 64*AST)
#define SKN (SVL + 64*AST)
#define ATT_SMEM (SKN + 256)   // 55552 B

__global__ __launch_bounds__(128)
void hyp_attn_mma(const __nv_bfloat16* __restrict__ qh, const __nv_bfloat16* __restrict__ ql,
                  const __nv_bfloat16* __restrict__ kh, const __nv_bfloat16* __restrict__ kl,
                  const __nv_bfloat16* __restrict__ vh, const __nv_bfloat16* __restrict__ vl,
                  const float* __restrict__ qn_, const float* __restrict__ kn_,
                  float* __restrict__ ctx,
                  const float* __restrict__ logc_p, const float* __restrict__ logb_p)
{
    extern __shared__ char smem[];
    const uint32_t sb = smem_u32(smem);
    const int tid = threadIdx.x;
    const int lane = tid & 31;
    const int w = tid >> 5;
    const int gi = lane >> 2, t4 = lane & 3;

    const int bh = blockIdx.y;
    const int qb = (gridDim.x - 1) - blockIdx.x;    // heavy blocks first
    const int r0 = qb * 64;

    const float c     = softplusf(*logc_p);
    const float beta2 = (softplusf(*logb_p) + 0.5f) * 1.44269504f;

    // --- load Q tile (hi/lo) into smem, then into per-warp A fragments ---
    for (int i = tid; i < 512; i += 128) {
        int r = i >> 3, ch = i & 7;
        size_t g = ((size_t)bh * N_ + r0 + r) * DH_ + ch * 8;
        *(uint4*)(smem + SQH + r * AST + ch * 16) = *(const uint4*)(qh + g);
        *(uint4*)(smem + SQL + r * AST + ch * 16) = *(const uint4*)(ql + g);
    }
    __syncthreads();

    const uint32_t aOff = (uint32_t)((w * 16 + (lane & 15)) * AST + (lane >> 4) * 16);
    uint32_t qfh[4][4], qfl[4][4];
#pragma unroll
    for (int s = 0; s < 4; s++) {
        LDSM_X4(qfh[s], sb + SQH + aOff + s * 32);
        LDSM_X4(qfl[s], sb + SQL + aOff + s * 32);
    }

    const float qn0 = qn_[bh * N_ + r0 + w * 16 + gi];
    const float qn1 = qn_[bh * N_ + r0 + w * 16 + gi + 8];

    float oacc[8][4];
#pragma unroll
    for (int f = 0; f < 8; f++)
#pragma unroll
        for (int r = 0; r < 4; r++) oacc[f][r] = 0.f;
    float l0 = 0.f, l1 = 0.f;

    const uint32_t bOffBase = (uint32_t)((((lane >> 4) & 1) * 8 + (lane & 7)) * AST
                                         + ((lane >> 3) & 1) * 16);

    for (int T = 0; T <= qb; T++) {
        __syncthreads();   // protect prior-tile smem readers
        // K tiles (straight copy)
        for (int i = tid; i < 512; i += 128) {
            int r = i >> 3, ch = i & 7;
            size_t g = ((size_t)bh * N_ + T * 64 + r) * DH_ + ch * 8;
            *(uint4*)(smem + SKH + r * AST + ch * 16) = *(const uint4*)(kh + g);
            *(uint4*)(smem + SKL + r * AST + ch * 16) = *(const uint4*)(kl + g);
        }
        // V tiles transposed: rows=dh, cols=key
        for (int i = tid; i < 512; i += 128) {
            int key = i >> 3, ch = i & 7;
            size_t g = ((size_t)bh * N_ + T * 64 + key) * DH_ + ch * 8;
            uint4 hv = *(const uint4*)(vh + g);
            uint4 lv = *(const uint4*)(vl + g);
            const unsigned short* hp = (const unsigned short*)&hv;
            const unsigned short* lp = (const unsigned short*)&lv;
#pragma unroll
            for (int e = 0; e < 8; e++) {
                int dh = ch * 8 + e;
                *(unsigned short*)(smem + SVH + dh * AST + key * 2) = hp[e];
                *(unsigned short*)(smem + SVL + dh * AST + key * 2) = lp[e];
            }
        }
        if (tid < 64) *(float*)(smem + SKN + tid * 4) = kn_[bh * N_ + T * 64 + tid];
        __syncthreads();

        // --- S = Q·K^T (3-product split), 8 n8 frags over 64 keys ---
        float sacc[8][4];
#pragma unroll
        for (int f = 0; f < 8; f++)
#pragma unroll
            for (int r = 0; r < 4; r++) sacc[f][r] = 0.f;

#pragma unroll
        for (int s = 0; s < 4; s++) {
#pragma unroll
            for (int n16 = 0; n16 < 4; n16++) {
                uint32_t kbh[4], kbl[4];
                uint32_t bo = bOffBase + (uint32_t)(n16 * 16 * AST) + s * 32;
                LDSM_X4(kbh, sb + SKH + bo);
                LDSM_X4(kbl, sb + SKL + bo);
#pragma unroll
                for (int half = 0; half < 2; half++) {
                    const int nf = n16 * 2 + half, pr = half * 2;
                    MMA_BF16(sacc[nf], qfh[s], kbh[pr], kbh[pr + 1]);
                    MMA_BF16(sacc[nf], qfh[s], kbl[pr], kbl[pr + 1]);
                    MMA_BF16(sacc[nf], qfl[s], kbh[pr], kbh[pr + 1]);
                }
            }
        }

        // --- score transform (in D-fragment registers) ---
        const bool diag = (T == qb);
#pragma unroll
        for (int f = 0; f < 8; f++) {
#pragma unroll
            for (int r = 0; r < 4; r++) {
                const int col = f * 8 + 2 * t4 + (r & 1);
                const int rl  = (r >> 1) ? (gi + 8) : gi;
                const float qnv = (r >> 1) ? qn1 : qn0;
                const float kn  = *(const float*)(smem + SKN + col * 4);
                const float dot = sacc[f][r];
                const float ns  = qnv + kn;
                float diff = fmaxf(fmaf(dot, -2.f, ns), 0.f);
                float arg  = diff + 1e-8f;
                float ed   = sqrt_apx(arg);
                float cns  = c * ns;
                float d_std = sqrt_apx(arg * (1.f + cns));
                float tt1 = fmaf(0.5f, cns, 1.f);
                float tt2 = fmaf(0.125f * cns, cns, tt1);
                float d_tay = ed * tt2;
                float lg = lg2_apx(ed);
                float d_asy = fmaf(0.69314718f, lg, 0.693f);
                d_asy = fmaf(0.25f, cns, d_asy);
                float dist = (ed < 0.1f) ? d_tay : ((ed > 2.0f) ? d_asy : d_std);
                float p = ex2_apx(-beta2 * dist);
                if (diag && (T * 64 + col > r0 + w * 16 + rl)) p = 0.f;
                if (r >> 1) l1 += p; else l0 += p;
                sacc[f][r] = p;
            }
        }

        // --- PV: repack P (split) to A-fragments, B = V^T (split) ---
#pragma unroll
        for (int s = 0; s < 4; s++) {
            uint32_t pah[4], pal[4];
            {
                const float* e = sacc[2 * s];
                const float* o = sacc[2 * s + 1];
                float pv[8] = { e[0], e[1], e[2], e[3], o[0], o[1], o[2], o[3] };
#pragma unroll
                for (int j = 0; j < 4; j++) {
                    uint32_t hpk; CVTPK(hpk, pv[2 * j], pv[2 * j + 1]);
                    pah[j] = hpk;
                    float f0 = pv[2 * j]     - __uint_as_float(hpk << 16);
                    float f1 = pv[2 * j + 1] - __uint_as_float(hpk & 0xFFFF0000u);
                    uint32_t lpk; CVTPK(lpk, f0, f1);
                    pal[j] = lpk;
                }
            }
#pragma unroll
            for (int n16 = 0; n16 < 4; n16++) {
                uint32_t vbh[4], vbl[4];
                uint32_t bo = bOffBase + (uint32_t)(n16 * 16 * AST) + s * 32;
                LDSM_X4(vbh, sb + SVH + bo);
                LDSM_X4(vbl, sb + SVL + bo);
#pragma unroll
                for (int half = 0; half < 2; half++) {
                    const int nf = n16 * 2 + half, pr = half * 2;
                    MMA_BF16(oacc[nf], pah, vbh[pr], vbh[pr + 1]);
                    MMA_BF16(oacc[nf], pah, vbl[pr], vbl[pr + 1]);
                    MMA_BF16(oacc[nf], pal, vbh[pr], vbh[pr + 1]);
                }
            }
        }
    }

    // --- reduce l across the 4 lanes sharing a row (t4 = 0..3) ---
    l0 += __shfl_xor_sync(0xFFFFFFFFu, l0, 1);
    l0 += __shfl_xor_sync(0xFFFFFFFFu, l0, 2);
    l1 += __shfl_xor_sync(0xFFFFFFFFu, l1, 1);
    l1 += __shfl_xor_sync(0xFFFFFFFFu, l1, 2);
    const float inv0 = 1.f / l0, inv1 = 1.f / l1;

    // --- store ctx[(b*N + row)*D + h*64 + dh] ---
    const int b = bh >> 4, h = bh & 15;
    const int row0 = r0 + w * 16 + gi;
    const int row1 = row0 + 8;
    float* out0 = ctx + ((size_t)b * N_ + row0) * D_ + h * DH_;
    float* out1 = ctx + ((size_t)b * N_ + row1) * D_ + h * DH_;
#pragma unroll
    for (int f = 0; f < 8; f++) {
        int col = f * 8 + 2 * t4;
        *(float2*)(out0 + col) = make_float2(oacc[f][0] * inv0, oacc[f][1] * inv0);
        *(float2*)(out1 + col) = make_float2(oacc[f][2] * inv1, oacc[f][3] * inv1);
    }
}

// ---------------------------------------------------------------------------
extern "C" void kernel_launch(void* const* d_in, const int* in_sizes, int n_in,
                              void* d_out, int out_size)
{
    const float* x     = (const float*)d_in[0];
    const float* Wq    = (const float*)d_in[1];
    const float* Wk    = (const float*)d_in[2];
    const float* Wv    = (const float*)d_in[3];
    const float* Wo    = (const float*)d_in[4];
    const float* log_c = (const float*)d_in[5];
    const float* log_b = (const float*)d_in[6];
    float* out = (float*)d_out;

    float *qptr, *kptr, *vptr, *ctxptr, *knp, *qnp;
    cudaGetSymbolAddress((void**)&qptr,   g_q);
    cudaGetSymbolAddress((void**)&kptr,   g_k);
    cudaGetSymbolAddress((void**)&vptr,   g_v);
    cudaGetSymbolAddress((void**)&ctxptr, g_ctx);
    cudaGetSymbolAddress((void**)&knp,    g_kn);
    cudaGetSymbolAddress((void**)&qnp,    g_qn);

    __nv_bfloat16 *xh, *xl, *wqh, *wql, *wkh, *wkl, *wvh, *wvl, *woh, *wol, *cth, *ctl;
    __nv_bfloat16 *qh, *ql, *kh, *kl, *vh, *vl;
    cudaGetSymbolAddress((void**)&xh,  g_xh);  cudaGetSymbolAddress((void**)&xl,  g_xl);
    cudaGetSymbolAddress((void**)&wqh, g_wqh); cudaGetSymbolAddress((void**)&wql, g_wql);
    cudaGetSymbolAddress((void**)&wkh, g_wkh); cudaGetSymbolAddress((void**)&wkl, g_wkl);
    cudaGetSymbolAddress((void**)&wvh, g_wvh); cudaGetSymbolAddress((void**)&wvl, g_wvl);
    cudaGetSymbolAddress((void**)&woh, g_woh); cudaGetSymbolAddress((void**)&wol, g_wol);
    cudaGetSymbolAddress((void**)&cth, g_cth); cudaGetSymbolAddress((void**)&ctl, g_ctl);
    cudaGetSymbolAddress((void**)&qh,  g_qh);  cudaGetSymbolAddress((void**)&ql,  g_ql);
    cudaGetSymbolAddress((void**)&kh,  g_kh);  cudaGetSymbolAddress((void**)&kl,  g_kl);
    cudaGetSymbolAddress((void**)&vh,  g_vh);  cudaGetSymbolAddress((void**)&vl,  g_vl);

    cudaFuncSetAttribute(hyp_attn_mma, cudaFuncAttributeMaxDynamicSharedMemorySize, ATT_SMEM);

    // Split inputs to bf16 hi/lo
    const int n4x = ROWS_ * D_ / 4;   // also = BHN_*DH_/4
    const int n4w = D_ * D_ / 4;
    split_bf16<<<n4x / 256, 256>>>(x,  xh,  xl,  n4x);
    split_bf16<<<n4w / 256, 256>>>(Wq, wqh, wql, n4w);
    split_bf16<<<n4w / 256, 256>>>(Wk, wkh, wkl, n4w);
    split_bf16<<<n4w / 256, 256>>>(Wv, wvh, wvl, n4w);
    split_bf16<<<n4w / 256, 256>>>(Wo, woh, wol, n4w);

    // QKV projections via HMMA (headLayout writes [B,H,N,Dh])
    gemm_tc<<<dim3(D_ / 64, ROWS_ / 128, 3), 256>>>(
        xh, xl, wqh, wql, wkh, wkl, wvh, wvl, qptr, kptr, vptr, 1);

    // Norms + attention operand splits
    row_norms<<<BHN_ / 8, 256>>>(qptr, qnp);
    row_norms<<<BHN_ / 8, 256>>>(kptr, knp);
    split_bf16<<<n4x / 256, 256>>>(qptr, qh, ql, n4x);
    split_bf16<<<n4x / 256, 256>>>(kptr, kh, kl, n4x);
    split_bf16<<<n4x / 256, 256>>>(vptr, vh, vl, n4x);

    // Tensor-core attention
    hyp_attn_mma<<<dim3(32, 32), 128, ATT_SMEM>>>(qh, ql, kh, kl, vh, vl,
                                                  qnp, knp, ctxptr, log_c, log_b);

    // Split ctx, then output projection
    split_bf16<<<n4x / 256, 256>>>(ctxptr, cth, ctl, n4x);
    gemm_tc<<<dim3(D_ / 64, ROWS_ / 128, 1), 256>>>(
        cth, ctl, woh, wol, woh, wol, woh, wol, out, out, out, 0);
}

// round 14
// speedup vs baseline: 3.1208x; 1.1624x over previous
#include <cuda_runtime.h>
#include <cuda_bf16.h>
#include <math.h>
#include <cstdint>

// Problem constants
#define B_  2
#define N_  2048
#define D_  1024
#define H_  16
#define DH_ 64
#define ROWS_ (B_*N_)          // 4096
#define BHN_  (B_*H_*N_)       // 65536

// ---------------------------------------------------------------------------
// MUFU approx helpers
// ---------------------------------------------------------------------------
__device__ __forceinline__ float sqrt_apx(float x) {
    float r; asm("sqrt.approx.f32 %0, %1;" : "=f"(r) : "f"(x)); return r;
}
__device__ __forceinline__ float lg2_apx(float x) {
    float r; asm("lg2.approx.f32 %0, %1;" : "=f"(r) : "f"(x)); return r;
}
__device__ __forceinline__ float ex2_apx(float x) {
    float r; asm("ex2.approx.f32 %0, %1;" : "=f"(r) : "f"(x)); return r;
}

// ---------------------------------------------------------------------------
// ldmatrix / mma.sync / cp.async helpers (baseline PTX)
// ---------------------------------------------------------------------------
__device__ __forceinline__ uint32_t smem_u32(const void* p) {
    uint32_t a;
    asm("{ .reg .u64 t; cvta.to.shared.u64 t, %1; cvt.u32.u64 %0, t; }" : "=r"(a) : "l"(p));
    return a;
}
#define LDSM_X4(r, addr) \
    asm volatile("ldmatrix.sync.aligned.m8n8.x4.shared.b16 {%0,%1,%2,%3}, [%4];" \
        : "=r"((r)[0]), "=r"((r)[1]), "=r"((r)[2]), "=r"((r)[3]) : "r"(addr))
#define LDSM_X4T(r, addr) \
    asm volatile("ldmatrix.sync.aligned.m8n8.x4.trans.shared.b16 {%0,%1,%2,%3}, [%4];" \
        : "=r"((r)[0]), "=r"((r)[1]), "=r"((r)[2]), "=r"((r)[3]) : "r"(addr))
#define MMA_BF16(d, a, b0v, b1v) \
    asm volatile("mma.sync.aligned.m16n8k16.row.col.f32.bf16.bf16.f32 " \
        "{%0,%1,%2,%3}, {%4,%5,%6,%7}, {%8,%9}, {%0,%1,%2,%3};" \
        : "+f"((d)[0]), "+f"((d)[1]), "+f"((d)[2]), "+f"((d)[3]) \
        : "r"((a)[0]), "r"((a)[1]), "r"((a)[2]), "r"((a)[3]), "r"(b0v), "r"(b1v))
#define CVTPK(d, p0, p1) \
    asm("cvt.rn.bf16x2.f32 %0, %1, %2;" : "=r"(d) : "f"(p1), "f"(p0))
#define CPA16(sm, gp) \
    asm volatile("cp.async.cg.shared.global [%0], [%1], 16;" :: "r"(sm), "l"(gp) : "memory")
#define CPA_COMMIT() asm volatile("cp.async.commit_group;" ::: "memory")
#define CPA_WAIT(n)  asm volatile("cp.async.wait_group %0;" :: "n"(n) : "memory")

// ---------------------------------------------------------------------------
// Scratch (static device globals — no allocation)
// ---------------------------------------------------------------------------
__device__ float g_q[BHN_*DH_];
__device__ float g_k[BHN_*DH_];
__device__ float g_v[BHN_*DH_];
__device__ float g_kn[BHN_];
__device__ float g_qn[BHN_];
__device__ __nv_bfloat16 g_xh[ROWS_*D_],  g_xl[ROWS_*D_];
__device__ __nv_bfloat16 g_wqh[D_*D_], g_wql[D_*D_];
__device__ __nv_bfloat16 g_wkh[D_*D_], g_wkl[D_*D_];
__device__ __nv_bfloat16 g_wvh[D_*D_], g_wvl[D_*D_];
__device__ __nv_bfloat16 g_woh[D_*D_], g_wol[D_*D_];
__device__ __nv_bfloat16 g_cth[ROWS_*D_], g_ctl[ROWS_*D_];
__device__ __nv_bfloat16 g_qh[BHN_*DH_], g_ql[BHN_*DH_];
__device__ __nv_bfloat16 g_kh[BHN_*DH_], g_kl[BHN_*DH_];
__device__ __nv_bfloat16 g_vh[BHN_*DH_], g_vl[BHN_*DH_];

__device__ __forceinline__ float softplusf(float x) {
    return (x > 20.f) ? x : log1pf(__expf(x));
}

// ---------------------------------------------------------------------------
// fp32 -> (bf16 hi, bf16 lo) split, 4 elements/thread (inputs/weights only)
// ---------------------------------------------------------------------------
__global__ void split_bf16(const float* __restrict__ s,
                           __nv_bfloat16* __restrict__ h,
                           __nv_bfloat16* __restrict__ l, int n4)
{
    int i = blockIdx.x * blockDim.x + threadIdx.x;
    if (i >= n4) return;
    float4 v = ((const float4*)s)[i];
    __nv_bfloat16 h0 = __float2bfloat16(v.x), h1 = __float2bfloat16(v.y);
    __nv_bfloat16 h2 = __float2bfloat16(v.z), h3 = __float2bfloat16(v.w);
    __nv_bfloat16 l0 = __float2bfloat16(v.x - __bfloat162float(h0));
    __nv_bfloat16 l1 = __float2bfloat16(v.y - __bfloat162float(h1));
    __nv_bfloat16 l2 = __float2bfloat16(v.z - __bfloat162float(h2));
    __nv_bfloat16 l3 = __float2bfloat16(v.w - __bfloat162float(h3));
    ushort4 hv = make_ushort4(__bfloat16_as_ushort(h0), __bfloat16_as_ushort(h1),
                              __bfloat16_as_ushort(h2), __bfloat16_as_ushort(h3));
    ushort4 lv = make_ushort4(__bfloat16_as_ushort(l0), __bfloat16_as_ushort(l1),
                              __bfloat16_as_ushort(l2), __bfloat16_as_ushort(l3));
    ((ushort4*)h)[i] = hv;
    ((ushort4*)l)[i] = lv;
}

// ---------------------------------------------------------------------------
// bf16-split HMMA GEMM, cp.async 2-stage pipeline, fused hi/lo split epilogue.
// C = A @ W^T (fp32) via Ah·Bh + Ah·Bl + Al·Bh. Tile 128x64x32, 256 thr.
// ---------------------------------------------------------------------------
#define GS_AH 0
#define GS_AL 10240
#define GS_BH 20480
#define GS_BL 25600
#define GS_STG 30720
#define GEMM_SMEM (2*GS_STG)   // 61440

#define GFILL(kk, bufo) do { \
    _Pragma("unroll") \
    for (int ii = 0; ii < 2; ii++) { \
        int idx = tid + ii * 256; int rr = idx >> 2, cch = idx & 3; \
        size_t g = (size_t)(rowBase + rr) * D_ + (kk) + cch * 8; \
        CPA16(sb + (bufo) + GS_AH + rr * 80 + cch * 16, Ah + g); \
        CPA16(sb + (bufo) + GS_AL + rr * 80 + cch * 16, Al + g); \
    } \
    { int rr = tid >> 2, cch = tid & 3; \
      size_t g = (size_t)(colBase + rr) * D_ + (kk) + cch * 8; \
      CPA16(sb + (bufo) + GS_BH + rr * 80 + cch * 16, Bh + g); \
      CPA16(sb + (bufo) + GS_BL + rr * 80 + cch * 16, Bl + g); } \
} while (0)

__global__ __launch_bounds__(256)
void gemm_tc(const __nv_bfloat16* __restrict__ Ah, const __nv_bfloat16* __restrict__ Al,
             const __nv_bfloat16* __restrict__ Bh0, const __nv_bfloat16* __restrict__ Bl0,
             const __nv_bfloat16* __restrict__ Bh1, const __nv_bfloat16* __restrict__ Bl1,
             const __nv_bfloat16* __restrict__ Bh2, const __nv_bfloat16* __restrict__ Bl2,
             float* __restrict__ C0, float* __restrict__ C1, float* __restrict__ C2,
             __nv_bfloat16* __restrict__ H0, __nv_bfloat16* __restrict__ L0,
             __nv_bfloat16* __restrict__ H1, __nv_bfloat16* __restrict__ L1,
             __nv_bfloat16* __restrict__ H2, __nv_bfloat16* __restrict__ L2,
             int headLayout)
{
    extern __shared__ char gsm[];
    const uint32_t sb = smem_u32(gsm);

    const int z = blockIdx.z;
    const __nv_bfloat16* __restrict__ Bh = (z == 0) ? Bh0 : (z == 1) ? Bh1 : Bh2;
    const __nv_bfloat16* __restrict__ Bl = (z == 0) ? Bl0 : (z == 1) ? Bl1 : Bl2;
    float* __restrict__ C = (z == 0) ? C0 : (z == 1) ? C1 : C2;
    __nv_bfloat16* __restrict__ Hd = (z == 0) ? H0 : (z == 1) ? H1 : H2;
    __nv_bfloat16* __restrict__ Ld = (z == 0) ? L0 : (z == 1) ? L1 : L2;

    const int tid  = threadIdx.x;
    const int lane = tid & 31;
    const int wid  = tid >> 5;
    const int wm   = wid & 3;
    const int wn   = wid >> 2;
    const int rowBase = blockIdx.y * 128;
    const int colBase = blockIdx.x * 64;

    const uint32_t aBase = (uint32_t)((wm * 32 + (lane & 15)) * 80 + (lane >> 4) * 16);
    const uint32_t bBase = (uint32_t)((wn * 32 + ((lane >> 4) & 1) * 8 + (lane & 7)) * 80
                                      + ((lane >> 3) & 1) * 16);

    float acc[2][4][4];
#pragma unroll
    for (int mf = 0; mf < 2; mf++)
#pragma unroll
        for (int nf = 0; nf < 4; nf++)
#pragma unroll
            for (int r = 0; r < 4; r++) acc[mf][nf][r] = 0.f;

    GFILL(0, 0);
    CPA_COMMIT();

    for (int kt = 0; kt < 32; kt++) {
        const uint32_t base = sb + (uint32_t)((kt & 1) * GS_STG);
        if (kt + 1 < 32) {
            GFILL((kt + 1) * 32, ((kt + 1) & 1) * GS_STG);
            CPA_COMMIT();
            CPA_WAIT(1);
        } else {
            CPA_WAIT(0);
        }
        __syncthreads();

#pragma unroll
        for (int k16 = 0; k16 < 2; k16++) {
            uint32_t ah[2][4], al[2][4], bh[2][4], bl[2][4];
#pragma unroll
            for (int mf = 0; mf < 2; mf++) {
                LDSM_X4(ah[mf], base + GS_AH + aBase + mf * 1280 + k16 * 32);
                LDSM_X4(al[mf], base + GS_AL + aBase + mf * 1280 + k16 * 32);
            }
#pragma unroll
            for (int n16 = 0; n16 < 2; n16++) {
                LDSM_X4(bh[n16], base + GS_BH + bBase + n16 * 1280 + k16 * 32);
                LDSM_X4(bl[n16], base + GS_BL + bBase + n16 * 1280 + k16 * 32);
            }
#pragma unroll
            for (int mf = 0; mf < 2; mf++)
#pragma unroll
                for (int nf = 0; nf < 4; nf++) {
                    const int n16 = nf >> 1, pr = (nf & 1) * 2;
                    MMA_BF16(acc[mf][nf], ah[mf], bh[n16][pr], bh[n16][pr + 1]);
                    MMA_BF16(acc[mf][nf], ah[mf], bl[n16][pr], bl[n16][pr + 1]);
                    MMA_BF16(acc[mf][nf], al[mf], bh[n16][pr], bh[n16][pr + 1]);
                }
        }
        __syncthreads();
    }

    const int gi = lane >> 2, t4 = lane & 3;
#pragma unroll
    for (int mf = 0; mf < 2; mf++) {
#pragma unroll
        for (int nf = 0; nf < 4; nf++) {
            int col = colBase + wn * 32 + nf * 8 + t4 * 2;
            int row0 = rowBase + wm * 32 + mf * 16 + gi;
            int row1 = row0 + 8;
            size_t off0, off1;
            if (headLayout) {
                int h = col >> 6, dh = col & 63;
                int b0 = row0 >> 11, n0 = row0 & 2047;
                int b1 = row1 >> 11, n1 = row1 & 2047;
                off0 = (((size_t)(b0 * H_ + h)) * N_ + n0) * DH_ + dh;
                off1 = (((size_t)(b1 * H_ + h)) * N_ + n1) * DH_ + dh;
            } else {
                off0 = (size_t)row0 * D_ + col;
                off1 = (size_t)row1 * D_ + col;
            }
            float2 v01 = make_float2(acc[mf][nf][0], acc[mf][nf][1]);
            float2 v23 = make_float2(acc[mf][nf][2], acc[mf][nf][3]);
            *(float2*)(C + off0) = v01;
            *(float2*)(C + off1) = v23;
            if (Hd) {
                uint32_t hp0; CVTPK(hp0, v01.x, v01.y);
                float lx = v01.x - __uint_as_float(hp0 << 16);
                float ly = v01.y - __uint_as_float(hp0 & 0xFFFF0000u);
                uint32_t lp0; CVTPK(lp0, lx, ly);
                *(uint32_t*)(Hd + off0) = hp0;
                *(uint32_t*)(Ld + off0) = lp0;
                uint32_t hp1; CVTPK(hp1, v23.x, v23.y);
                lx = v23.x - __uint_as_float(hp1 << 16);
                ly = v23.y - __uint_as_float(hp1 & 0xFFFF0000u);
                uint32_t lp1; CVTPK(lp1, lx, ly);
                *(uint32_t*)(Hd + off1) = hp1;
                *(uint32_t*)(Ld + off1) = lp1;
            }
        }
    }
}

// ---------------------------------------------------------------------------
// Row squared-norms: one warp per 64-elem row.
// ---------------------------------------------------------------------------
__global__ void row_norms(const float* __restrict__ src, float* __restrict__ dst)
{
    int gw = (blockIdx.x * blockDim.x + threadIdx.x) >> 5;
    int lane = threadIdx.x & 31;
    if (gw >= BHN_) return;
    const float* r = src + (size_t)gw * DH_;
    float a = r[lane], b = r[lane + 32];
    float s = a * a + b * b;
#pragma unroll
    for (int off = 16; off > 0; off >>= 1)
        s += __shfl_xor_sync(0xFFFFFFFFu, s, off);
    if (lane == 0) dst[gw] = s;
}

// ---------------------------------------------------------------------------
// Tensor-core hyperbolic flash attention (V straight + ldmatrix.trans).
// Grid (32 qblocks reversed, 32 bh), 128 threads (4 warps, m16 each).
// Writes ctx hi/lo bf16 directly (fused split).
// ---------------------------------------------------------------------------
#define AST 144        // bytes per smem row
#define SQH 0
#define SQL (SQH + 64*AST)
#define SKH (SQL + 64*AST)
#define SKL (SKH + 64*AST)
#define SVH (SKL + 64*AST)     // straight V: rows=key, cols=dh
#define SVL (SVH + 64*AST)
#define SKN (SVL + 64*AST)
#define ATT_SMEM (SKN + 256)   // 55552 B

__global__ __launch_bounds__(128)
void hyp_attn_mma(const __nv_bfloat16* __restrict__ qh, const __nv_bfloat16* __restrict__ ql,
                  const __nv_bfloat16* __restrict__ kh, const __nv_bfloat16* __restrict__ kl,
                  const __nv_bfloat16* __restrict__ vh, const __nv_bfloat16* __restrict__ vl,
                  const float* __restrict__ qn_, const float* __restrict__ kn_,
                  __nv_bfloat16* __restrict__ cth, __nv_bfloat16* __restrict__ ctl,
                  const float* __restrict__ logc_p, const float* __restrict__ logb_p)
{
    extern __shared__ char smem[];
    const uint32_t sb = smem_u32(smem);
    const int tid = threadIdx.x;
    const int lane = tid & 31;
    const int w = tid >> 5;
    const int gi = lane >> 2, t4 = lane & 3;

    const int bh = blockIdx.y;
    const int qb = (gridDim.x - 1) - blockIdx.x;    // heavy blocks first
    const int r0 = qb * 64;

    const float c     = softplusf(*logc_p);
    const float beta2 = (softplusf(*logb_p) + 0.5f) * 1.44269504f;

    // --- load Q tile (hi/lo) into smem, then into per-warp A fragments ---
    for (int i = tid; i < 512; i += 128) {
        int r = i >> 3, ch = i & 7;
        size_t g = ((size_t)bh * N_ + r0 + r) * DH_ + ch * 8;
        *(uint4*)(smem + SQH + r * AST + ch * 16) = *(const uint4*)(qh + g);
        *(uint4*)(smem + SQL + r * AST + ch * 16) = *(const uint4*)(ql + g);
    }
    __syncthreads();

    const uint32_t aOff = (uint32_t)((w * 16 + (lane & 15)) * AST + (lane >> 4) * 16);
    uint32_t qfh[4][4], qfl[4][4];
#pragma unroll
    for (int s = 0; s < 4; s++) {
        LDSM_X4(qfh[s], sb + SQH + aOff + s * 32);
        LDSM_X4(qfl[s], sb + SQL + aOff + s * 32);
    }

    const float qn0 = qn_[bh * N_ + r0 + w * 16 + gi];
    const float qn1 = qn_[bh * N_ + r0 + w * 16 + gi + 8];

    float oacc[8][4];
#pragma unroll
    for (int f = 0; f < 8; f++)
#pragma unroll
        for (int r = 0; r < 4; r++) oacc[f][r] = 0.f;
    float l0 = 0.f, l1 = 0.f;

    // K B-operand lane offset (non-trans, rows = key)
    const uint32_t bOffBase = (uint32_t)((((lane >> 4) & 1) * 8 + (lane & 7)) * AST
                                         + ((lane >> 3) & 1) * 16);
    // V B-operand lane offset (trans, rows = key, cols = dh)
    const uint32_t vOffBase = (uint32_t)((lane & 15) * AST + (lane >> 4) * 16);

    for (int T = 0; T <= qb; T++) {
        __syncthreads();   // protect prior-tile smem readers
        for (int i = tid; i < 512; i += 128) {
            int r = i >> 3, ch = i & 7;
            size_t g = ((size_t)bh * N_ + T * 64 + r) * DH_ + ch * 8;
            *(uint4*)(smem + SKH + r * AST + ch * 16) = *(const uint4*)(kh + g);
            *(uint4*)(smem + SKL + r * AST + ch * 16) = *(const uint4*)(kl + g);
            *(uint4*)(smem + SVH + r * AST + ch * 16) = *(const uint4*)(vh + g);
            *(uint4*)(smem + SVL + r * AST + ch * 16) = *(const uint4*)(vl + g);
        }
        if (tid < 64) *(float*)(smem + SKN + tid * 4) = kn_[bh * N_ + T * 64 + tid];
        __syncthreads();

        // --- S = Q·K^T (3-product split) ---
        float sacc[8][4];
#pragma unroll
        for (int f = 0; f < 8; f++)
#pragma unroll
            for (int r = 0; r < 4; r++) sacc[f][r] = 0.f;

#pragma unroll
        for (int s = 0; s < 4; s++) {
#pragma unroll
            for (int n16 = 0; n16 < 4; n16++) {
                uint32_t kbh[4], kbl[4];
                uint32_t bo = bOffBase + (uint32_t)(n16 * 16 * AST) + s * 32;
                LDSM_X4(kbh, sb + SKH + bo);
                LDSM_X4(kbl, sb + SKL + bo);
#pragma unroll
                for (int half = 0; half < 2; half++) {
                    const int nf = n16 * 2 + half, pr = half * 2;
                    MMA_BF16(sacc[nf], qfh[s], kbh[pr], kbh[pr + 1]);
                    MMA_BF16(sacc[nf], qfh[s], kbl[pr], kbl[pr + 1]);
                    MMA_BF16(sacc[nf], qfl[s], kbh[pr], kbh[pr + 1]);
                }
            }
        }

        // --- score transform ---
        const bool diag = (T == qb);
#pragma unroll
        for (int f = 0; f < 8; f++) {
#pragma unroll
            for (int r = 0; r < 4; r++) {
                const int col = f * 8 + 2 * t4 + (r & 1);
                const int rl  = (r >> 1) ? (gi + 8) : gi;
                const float qnv = (r >> 1) ? qn1 : qn0;
                const float kn  = *(const float*)(smem + SKN + col * 4);
                const float dot = sacc[f][r];
                const float ns  = qnv + kn;
                float diff = fmaxf(fmaf(dot, -2.f, ns), 0.f);
                float arg  = diff + 1e-8f;
                float ed   = sqrt_apx(arg);
                float cns  = c * ns;
                float d_std = sqrt_apx(arg * (1.f + cns));
                float tt1 = fmaf(0.5f, cns, 1.f);
                float tt2 = fmaf(0.125f * cns, cns, tt1);
                float d_tay = ed * tt2;
                float lg = lg2_apx(ed);
                float d_asy = fmaf(0.69314718f, lg, 0.693f);
                d_asy = fmaf(0.25f, cns, d_asy);
                float dist = (ed < 0.1f) ? d_tay : ((ed > 2.0f) ? d_asy : d_std);
                float p = ex2_apx(-beta2 * dist);
                if (diag && (T * 64 + col > r0 + w * 16 + rl)) p = 0.f;
                if (r >> 1) l1 += p; else l0 += p;
                sacc[f][r] = p;
            }
        }

        // --- PV: repack P (split) to A-fragments; B = V via trans ldmatrix ---
#pragma unroll
        for (int s = 0; s < 4; s++) {
            uint32_t pah[4], pal[4];
            {
                const float* e = sacc[2 * s];
                const float* o = sacc[2 * s + 1];
                float pv[8] = { e[0], e[1], e[2], e[3], o[0], o[1], o[2], o[3] };
#pragma unroll
                for (int j = 0; j < 4; j++) {
                    uint32_t hpk; CVTPK(hpk, pv[2 * j], pv[2 * j + 1]);
                    pah[j] = hpk;
                    float f0 = pv[2 * j]     - __uint_as_float(hpk << 16);
                    float f1 = pv[2 * j + 1] - __uint_as_float(hpk & 0xFFFF0000u);
                    uint32_t lpk; CVTPK(lpk, f0, f1);
                    pal[j] = lpk;
                }
            }
#pragma unroll
            for (int n16 = 0; n16 < 4; n16++) {
                uint32_t vbh[4], vbl[4];
                uint32_t vo = vOffBase + (uint32_t)(s * 16 * AST) + n16 * 32;
                LDSM_X4T(vbh, sb + SVH + vo);
                LDSM_X4T(vbl, sb + SVL + vo);
#pragma unroll
                for (int half = 0; half < 2; half++) {
                    const int nf = n16 * 2 + half, pr = half * 2;
                    MMA_BF16(oacc[nf], pah, vbh[pr], vbh[pr + 1]);
                    MMA_BF16(oacc[nf], pah, vbl[pr], vbl[pr + 1]);
                    MMA_BF16(oacc[nf], pal, vbh[pr], vbh[pr + 1]);
                }
            }
        }
    }

    // --- reduce l across the 4 lanes sharing a row ---
    l0 += __shfl_xor_sync(0xFFFFFFFFu, l0, 1);
    l0 += __shfl_xor_sync(0xFFFFFFFFu, l0, 2);
    l1 += __shfl_xor_sync(0xFFFFFFFFu, l1, 1);
    l1 += __shfl_xor_sync(0xFFFFFFFFu, l1, 2);
    const float inv0 = 1.f / l0, inv1 = 1.f / l1;

    // --- store ctx hi/lo bf16 ---
    const int b = bh >> 4, h = bh & 15;
    const int row0 = r0 + w * 16 + gi;
    const int row1 = row0 + 8;
    const size_t o0 = ((size_t)b * N_ + row0) * D_ + h * DH_;
    const size_t o1 = ((size_t)b * N_ + row1) * D_ + h * DH_;
#pragma unroll
    for (int f = 0; f < 8; f++) {
        int col = f * 8 + 2 * t4;
        float a0 = oacc[f][0] * inv0, a1 = oacc[f][1] * inv0;
        uint32_t hp0; CVTPK(hp0, a0, a1);
        float lx = a0 - __uint_as_float(hp0 << 16);
        float ly = a1 - __uint_as_float(hp0 & 0xFFFF0000u);
        uint32_t lp0; CVTPK(lp0, lx, ly);
        *(uint32_t*)(cth + o0 + col) = hp0;
        *(uint32_t*)(ctl + o0 + col) = lp0;
        float b0v = oacc[f][2] * inv1, b1v = oacc[f][3] * inv1;
        uint32_t hp1; CVTPK(hp1, b0v, b1v);
        lx = b0v - __uint_as_float(hp1 << 16);
        ly = b1v - __uint_as_float(hp1 & 0xFFFF0000u);
        uint32_t lp1; CVTPK(lp1, lx, ly);
        *(uint32_t*)(cth + o1 + col) = hp1;
        *(uint32_t*)(ctl + o1 + col) = lp1;
    }
}

// ---------------------------------------------------------------------------
extern "C" void kernel_launch(void* const* d_in, const int* in_sizes, int n_in,
                              void* d_out, int out_size)
{
    const float* x     = (const float*)d_in[0];
    const float* Wq    = (const float*)d_in[1];
    const float* Wk    = (const float*)d_in[2];
    const float* Wv    = (const float*)d_in[3];
    const float* Wo    = (const float*)d_in[4];
    const float* log_c = (const float*)d_in[5];
    const float* log_b = (const float*)d_in[6];
    float* out = (float*)d_out;

    float *qptr, *kptr, *vptr, *knp, *qnp;
    cudaGetSymbolAddress((void**)&qptr, g_q);
    cudaGetSymbolAddress((void**)&kptr, g_k);
    cudaGetSymbolAddress((void**)&vptr, g_v);
    cudaGetSymbolAddress((void**)&knp,  g_kn);
    cudaGetSymbolAddress((void**)&qnp,  g_qn);

    __nv_bfloat16 *xh, *xl, *wqh, *wql, *wkh, *wkl, *wvh, *wvl, *woh, *wol, *cth, *ctl;
    __nv_bfloat16 *qh, *ql, *kh, *kl, *vh, *vl;
    cudaGetSymbolAddress((void**)&xh,  g_xh);  cudaGetSymbolAddress((void**)&xl,  g_xl);
    cudaGetSymbolAddress((void**)&wqh, g_wqh); cudaGetSymbolAddress((void**)&wql, g_wql);
    cudaGetSymbolAddress((void**)&wkh, g_wkh); cudaGetSymbolAddress((void**)&wkl, g_wkl);
    cudaGetSymbolAddress((void**)&wvh, g_wvh); cudaGetSymbolAddress((void**)&wvl, g_wvl);
    cudaGetSymbolAddress((void**)&woh, g_woh); cudaGetSymbolAddress((void**)&wol, g_wol);
    cudaGetSymbolAddress((void**)&cth, g_cth); cudaGetSymbolAddress((void**)&ctl, g_ctl);
    cudaGetSymbolAddress((void**)&qh,  g_qh);  cudaGetSymbolAddress((void**)&ql,  g_ql);
    cudaGetSymbolAddress((void**)&kh,  g_kh);  cudaGetSymbolAddress((void**)&kl,  g_kl);
    cudaGetSymbolAddress((void**)&vh,  g_vh);  cudaGetSymbolAddress((void**)&vl,  g_vl);

    cudaFuncSetAttribute(gemm_tc, cudaFuncAttributeMaxDynamicSharedMemorySize, GEMM_SMEM);
    cudaFuncSetAttribute(hyp_attn_mma, cudaFuncAttributeMaxDynamicSharedMemorySize, ATT_SMEM);

    // Split inputs to bf16 hi/lo
    const int n4x = ROWS_ * D_ / 4;
    const int n4w = D_ * D_ / 4;
    split_bf16<<<n4x / 256, 256>>>(x,  xh,  xl,  n4x);
    split_bf16<<<n4w / 256, 256>>>(Wq, wqh, wql, n4w);
    split_bf16<<<n4w / 256, 256>>>(Wk, wkh, wkl, n4w);
    split_bf16<<<n4w / 256, 256>>>(Wv, wvh, wvl, n4w);
    split_bf16<<<n4w / 256, 256>>>(Wo, woh, wol, n4w);

    // QKV projections via HMMA, fused hi/lo split epilogue
    gemm_tc<<<dim3(D_ / 64, ROWS_ / 128, 3), 256, GEMM_SMEM>>>(
        xh, xl, wqh, wql, wkh, wkl, wvh, wvl, qptr, kptr, vptr,
        qh, ql, kh, kl, vh, vl, 1);

    // Norms
    row_norms<<<BHN_ / 8, 256>>>(qptr, qnp);
    row_norms<<<BHN_ / 8, 256>>>(kptr, knp);

    // Tensor-core attention (writes ctx hi/lo directly)
    hyp_attn_mma<<<dim3(32, 32), 128, ATT_SMEM>>>(qh, ql, kh, kl, vh, vl,
                                                  qnp, knp, cth, ctl, log_c, log_b);

    // Output projection (fp32 out only)
    gemm_tc<<<dim3(D_ / 64, ROWS_ / 128, 1), 256, GEMM_SMEM>>>(
        cth, ctl, woh, wol, woh, wol, woh, wol, out, out, out,
        (__nv_bfloat16*)nullptr, (__nv_bfloat16*)nullptr,
        (__nv_bfloat16*)nullptr, (__nv_bfloat16*)nullptr,
        (__nv_bfloat16*)nullptr, (__nv_bfloat16*)nullptr, 0);
}